// round 1
// baseline (speedup 1.0000x reference)
#include <cuda_runtime.h>

#define NN   50000
#define EE   800000
#define ETOT (EE + NN)
#define GG   128
#define KIN  38
#define CH1  256
#define CH2  128
#define SCB  1024

// ---------------- static device scratch (no allocations allowed) ----------------
__device__ float g_xl1[NN * CH1];
__device__ float g_xr1[NN * CH1];
__device__ float g_h1 [NN * CH1];
__device__ float g_xl2[NN * CH2];
__device__ float g_xr2[NN * CH2];
__device__ float g_h2 [NN * CH2];
__device__ int   g_deg[NN];
__device__ int   g_incl[NN];
__device__ int   g_off[NN + 1];
__device__ int   g_wcur[NN];
__device__ int   g_part[64];
__device__ int   g_srcs[ETOT];
__device__ float g_sums[GG * CH2];
__device__ int   g_cnt[GG];

// ---------------- init / CSR build ----------------
__global__ void k_init() {
    int i = blockIdx.x * blockDim.x + threadIdx.x;
    if (i < NN) g_deg[i] = 0;
    if (i < GG * CH2) g_sums[i] = 0.f;
    if (i < GG) g_cnt[i] = 0;
}

__global__ void k_degree(const int* __restrict__ ei) {
    int e = blockIdx.x * blockDim.x + threadIdx.x;
    if (e >= ETOT) return;
    int dst = (e < EE) ? ei[EE + e] : (e - EE);
    atomicAdd(&g_deg[dst], 1);
}

__global__ void k_scan1() {
    __shared__ int sh[SCB];
    int i = blockIdx.x * SCB + threadIdx.x;
    int v = (i < NN) ? g_deg[i] : 0;
    sh[threadIdx.x] = v;
    __syncthreads();
    for (int off = 1; off < SCB; off <<= 1) {
        int t = (threadIdx.x >= off) ? sh[threadIdx.x - off] : 0;
        __syncthreads();
        sh[threadIdx.x] += t;
        __syncthreads();
    }
    if (i < NN) g_incl[i] = sh[threadIdx.x];
    if (threadIdx.x == SCB - 1) g_part[blockIdx.x] = sh[threadIdx.x];
}

__global__ void k_scan2(int nb) {
    __shared__ int sh[64];
    int v = (threadIdx.x < nb) ? g_part[threadIdx.x] : 0;
    sh[threadIdx.x] = v;
    __syncthreads();
    for (int off = 1; off < 64; off <<= 1) {
        int t = (threadIdx.x >= off) ? sh[threadIdx.x - off] : 0;
        __syncthreads();
        sh[threadIdx.x] += t;
        __syncthreads();
    }
    g_part[threadIdx.x] = sh[threadIdx.x] - v;  // exclusive prefix of block totals
}

__global__ void k_scan3() {
    int i = blockIdx.x * SCB + threadIdx.x;
    if (i < NN) {
        int excl = g_incl[i] - g_deg[i] + g_part[blockIdx.x];
        g_off[i]  = excl;
        g_wcur[i] = excl;
    }
    if (i == 0) g_off[NN] = ETOT;
}

__global__ void k_scatter(const int* __restrict__ ei) {
    int e = blockIdx.x * blockDim.x + threadIdx.x;
    if (e >= ETOT) return;
    int src, dst;
    if (e < EE) { src = ei[e]; dst = ei[EE + e]; }
    else        { src = e - EE; dst = src; }
    int pos = atomicAdd(&g_wcur[dst], 1);
    g_srcs[pos] = src;
}

// ---------------- fp32 tiled GEMM: C[M,N] = A[M,K] @ W[K,N] + bias ----------------
// BM=BN=128, BK=8, 256 threads, 8x8 micro-tile per thread (split 4+4 at offset 64)
__global__ __launch_bounds__(256) void gemm_bias(
    const float* __restrict__ A, const float* __restrict__ W,
    const float* __restrict__ bias, float* __restrict__ C,
    int M, int K, int N) {
    __shared__ float As[8][128];
    __shared__ float Ws[8][128];
    int tid = threadIdx.x;
    int tx = tid & 15, ty = tid >> 4;
    int rowBase = blockIdx.y * 128;
    int colBase = blockIdx.x * 128;
    float acc[8][8];
#pragma unroll
    for (int i = 0; i < 8; i++)
#pragma unroll
        for (int j = 0; j < 8; j++) acc[i][j] = 0.f;

    int ar = tid >> 1, akb = (tid & 1) * 4;
    int wk = tid >> 5, wc = (tid & 31) * 4;

    for (int k0 = 0; k0 < K; k0 += 8) {
#pragma unroll
        for (int j = 0; j < 4; j++) {
            int gk = k0 + akb + j;
            int gr = rowBase + ar;
            As[akb + j][ar] = (gr < M && gk < K) ? A[(long)gr * K + gk] : 0.f;
        }
        if (k0 + wk < K) {
            *(float4*)&Ws[wk][wc] =
                *(const float4*)&W[(long)(k0 + wk) * N + colBase + wc];
        } else {
            Ws[wk][wc] = 0.f; Ws[wk][wc + 1] = 0.f;
            Ws[wk][wc + 2] = 0.f; Ws[wk][wc + 3] = 0.f;
        }
        __syncthreads();
#pragma unroll
        for (int kk = 0; kk < 8; kk++) {
            float4 a0 = *(const float4*)&As[kk][ty * 4];
            float4 a1 = *(const float4*)&As[kk][64 + ty * 4];
            float4 w0 = *(const float4*)&Ws[kk][tx * 4];
            float4 w1 = *(const float4*)&Ws[kk][64 + tx * 4];
            float a[8] = {a0.x, a0.y, a0.z, a0.w, a1.x, a1.y, a1.z, a1.w};
            float w[8] = {w0.x, w0.y, w0.z, w0.w, w1.x, w1.y, w1.z, w1.w};
#pragma unroll
            for (int i = 0; i < 8; i++)
#pragma unroll
                for (int j = 0; j < 8; j++) acc[i][j] += a[i] * w[j];
        }
        __syncthreads();
    }
    float4 b0 = *(const float4*)&bias[colBase + tx * 4];
    float4 b1 = *(const float4*)&bias[colBase + 64 + tx * 4];
    float bb[8] = {b0.x, b0.y, b0.z, b0.w, b1.x, b1.y, b1.z, b1.w};
#pragma unroll
    for (int i = 0; i < 8; i++) {
        int r = rowBase + ((i < 4) ? (ty * 4 + i) : (64 + ty * 4 + (i - 4)));
        if (r >= M) continue;
        float4 o0 = make_float4(acc[i][0] + bb[0], acc[i][1] + bb[1],
                                acc[i][2] + bb[2], acc[i][3] + bb[3]);
        float4 o1 = make_float4(acc[i][4] + bb[4], acc[i][5] + bb[5],
                                acc[i][6] + bb[6], acc[i][7] + bb[7]);
        *(float4*)&C[(long)r * N + colBase + tx * 4] = o0;
        *(float4*)&C[(long)r * N + colBase + 64 + tx * 4] = o1;
    }
}

// ---------------- GATv2 layer: warp-per-dst-node, online softmax, single edge pass ----------------
// Channel layout: flat channel = h*Cph + c. Lane owns float4 indices {lane, lane+32}.
// CH=256,H=4: vec v head = 2v + (lane>>4). CH=128,H=1: head 0.
template <int HEADS, int CH>
__global__ __launch_bounds__(256) void gat_kernel(
    const float4* __restrict__ xl4, const float4* __restrict__ xr4,
    const float4* __restrict__ att4, const float4* __restrict__ bias4,
    float4* __restrict__ out4) {
    constexpr int V  = CH / 128;
    constexpr int C4 = CH / 4;
    int gw   = (blockIdx.x * blockDim.x + threadIdx.x) >> 5;
    int lane = threadIdx.x & 31;
    if (gw >= NN) return;
    const int d = gw;

    float4 xr[V], at[V];
#pragma unroll
    for (int v = 0; v < V; v++) {
        xr[v] = xr4[(long)d * C4 + lane + 32 * v];
        at[v] = att4[lane + 32 * v];
    }
    float m[HEADS], den[HEADS];
#pragma unroll
    for (int h = 0; h < HEADS; h++) { m[h] = -1e30f; den[h] = 0.f; }
    float4 acc[V];
#pragma unroll
    for (int v = 0; v < V; v++) acc[v] = make_float4(0.f, 0.f, 0.f, 0.f);

    int beg = g_off[d], end = g_off[d + 1];
    for (int i = beg; i < end; i++) {
        int s = g_srcs[i];
        float4 xv[V];
        float part[V];
#pragma unroll
        for (int v = 0; v < V; v++) {
            float4 x = xl4[(long)s * C4 + lane + 32 * v];
            xv[v] = x;
            float4 r = xr[v], a = at[v];
            float t, p = 0.f;
            t = x.x + r.x; t = fmaxf(t, 0.f) + 0.2f * fminf(t, 0.f); p += t * a.x;
            t = x.y + r.y; t = fmaxf(t, 0.f) + 0.2f * fminf(t, 0.f); p += t * a.y;
            t = x.z + r.z; t = fmaxf(t, 0.f) + 0.2f * fminf(t, 0.f); p += t * a.z;
            t = x.w + r.w; t = fmaxf(t, 0.f) + 0.2f * fminf(t, 0.f); p += t * a.w;
            part[v] = p;
        }
        float logit[HEADS];
        if constexpr (HEADS == 1) {
            float p = part[0];
#pragma unroll
            for (int o = 16; o > 0; o >>= 1) p += __shfl_xor_sync(0xffffffffu, p, o);
            logit[0] = p;
        } else {
#pragma unroll
            for (int v = 0; v < V; v++) {
                float p = part[v];
                p += __shfl_xor_sync(0xffffffffu, p, 1);
                p += __shfl_xor_sync(0xffffffffu, p, 2);
                p += __shfl_xor_sync(0xffffffffu, p, 4);
                p += __shfl_xor_sync(0xffffffffu, p, 8);
                logit[2 * v]     = __shfl_sync(0xffffffffu, p, 0);
                logit[2 * v + 1] = __shfl_sync(0xffffffffu, p, 16);
            }
        }
        float sc[HEADS], wt[HEADS];
#pragma unroll
        for (int h = 0; h < HEADS; h++) {
            float nm = fmaxf(m[h], logit[h]);
            sc[h] = __expf(m[h] - nm);
            wt[h] = __expf(logit[h] - nm);
            den[h] = den[h] * sc[h] + wt[h];
            m[h] = nm;
        }
#pragma unroll
        for (int v = 0; v < V; v++) {
            float s0, w0;
            if constexpr (HEADS == 1) { s0 = sc[0]; w0 = wt[0]; }
            else {
                s0 = (lane < 16) ? sc[2 * v] : sc[2 * v + 1];
                w0 = (lane < 16) ? wt[2 * v] : wt[2 * v + 1];
            }
            acc[v].x = acc[v].x * s0 + w0 * xv[v].x;
            acc[v].y = acc[v].y * s0 + w0 * xv[v].y;
            acc[v].z = acc[v].z * s0 + w0 * xv[v].z;
            acc[v].w = acc[v].w * s0 + w0 * xv[v].w;
        }
    }
#pragma unroll
    for (int v = 0; v < V; v++) {
        float inv;
        if constexpr (HEADS == 1) inv = 1.f / (den[0] + 1e-16f);
        else {
            float dd = (lane < 16) ? den[2 * v] : den[2 * v + 1];
            inv = 1.f / (dd + 1e-16f);
        }
        float4 b = bias4[lane + 32 * v];
        float4 o;
        o.x = fmaxf(acc[v].x * inv + b.x, 0.f);
        o.y = fmaxf(acc[v].y * inv + b.y, 0.f);
        o.z = fmaxf(acc[v].z * inv + b.z, 0.f);
        o.w = fmaxf(acc[v].w * inv + b.w, 0.f);
        out4[(long)d * C4 + lane + 32 * v] = o;
    }
}

// ---------------- global mean pool ----------------
__global__ void k_pool(const float* __restrict__ h2, const int* __restrict__ batch) {
    int t = blockIdx.x * blockDim.x + threadIdx.x;
    int w = t >> 5, lane = t & 31;
    if (w >= NN) return;
    int g = batch[w];
#pragma unroll
    for (int c = 0; c < CH2 / 32; c++)
        atomicAdd(&g_sums[g * CH2 + lane + 32 * c], h2[(long)w * CH2 + lane + 32 * c]);
    if (lane == 0) atomicAdd(&g_cnt[g], 1);
}

__global__ void k_final(float* __restrict__ out) {
    int i = blockIdx.x * blockDim.x + threadIdx.x;
    if (i < GG * CH2) {
        int g = i / CH2;
        float c = (float)g_cnt[g];
        out[i] = g_sums[i] / fmaxf(c, 1.f);
    }
}

// ---------------- launch ----------------
extern "C" void kernel_launch(void* const* d_in, const int* in_sizes, int n_in,
                              void* d_out, int out_size) {
    const float* x     = (const float*)d_in[0];
    const int*   ei    = (const int*)d_in[1];
    const int*   batch = (const int*)d_in[2];
    const float* Wl1   = (const float*)d_in[3];
    const float* bl1   = (const float*)d_in[4];
    const float* Wr1   = (const float*)d_in[5];
    const float* br1   = (const float*)d_in[6];
    const float* att1  = (const float*)d_in[7];
    const float* bias1 = (const float*)d_in[8];
    const float* Wl2   = (const float*)d_in[9];
    const float* bl2   = (const float*)d_in[10];
    const float* Wr2   = (const float*)d_in[11];
    const float* br2   = (const float*)d_in[12];
    const float* att2  = (const float*)d_in[13];
    const float* bias2 = (const float*)d_in[14];

    float *xl1, *xr1, *h1, *xl2, *xr2, *h2;
    cudaGetSymbolAddress((void**)&xl1, g_xl1);
    cudaGetSymbolAddress((void**)&xr1, g_xr1);
    cudaGetSymbolAddress((void**)&h1,  g_h1);
    cudaGetSymbolAddress((void**)&xl2, g_xl2);
    cudaGetSymbolAddress((void**)&xr2, g_xr2);
    cudaGetSymbolAddress((void**)&h2,  g_h2);

    int nb = (NN + SCB - 1) / SCB;

    k_init<<<(NN + 255) / 256, 256>>>();
    k_degree<<<(ETOT + 255) / 256, 256>>>(ei);
    k_scan1<<<nb, SCB>>>();
    k_scan2<<<1, 64>>>(nb);
    k_scan3<<<nb, SCB>>>();
    k_scatter<<<(ETOT + 255) / 256, 256>>>(ei);

    dim3 g1(CH1 / 128, (NN + 127) / 128);
    gemm_bias<<<g1, 256>>>(x, Wl1, bl1, xl1, NN, KIN, CH1);
    gemm_bias<<<g1, 256>>>(x, Wr1, br1, xr1, NN, KIN, CH1);

    gat_kernel<4, 256><<<(NN + 7) / 8, 256>>>(
        (const float4*)xl1, (const float4*)xr1,
        (const float4*)att1, (const float4*)bias1, (float4*)h1);

    dim3 g2(CH2 / 128, (NN + 127) / 128);
    gemm_bias<<<g2, 256>>>(h1, Wl2, bl2, xl2, NN, CH1, CH2);
    gemm_bias<<<g2, 256>>>(h1, Wr2, br2, xr2, NN, CH1, CH2);

    gat_kernel<1, 128><<<(NN + 7) / 8, 256>>>(
        (const float4*)xl2, (const float4*)xr2,
        (const float4*)att2, (const float4*)bias2, (float4*)h2);

    k_pool<<<(NN * 32 + 255) / 256, 256>>>(h2, batch);
    k_final<<<(GG * CH2 + 255) / 256, 256>>>((float*)d_out);
}

// round 2
// speedup vs baseline: 1.2539x; 1.2539x over previous
#include <cuda_runtime.h>

#define NN   50000
#define EE   800000
#define ETOT (EE + NN)
#define GG   128
#define KIN  38
#define CH1  256
#define CH2  128
#define SCB  1024

// ---------------- static device scratch (zero-initialized at load; k_reset
// restores the zero invariant at the end of every launch sequence) ----------
__device__ float g_xlr1[NN * 2 * CH1];
__device__ float g_h1  [NN * CH1];
__device__ float g_xlr2[NN * 2 * CH2];
__device__ float g_h2  [NN * CH2];
__device__ int   g_deg[NN];
__device__ int   g_incl[NN];
__device__ int   g_off[NN + 1];
__device__ int   g_wcur[NN];
__device__ int   g_part[64];
__device__ int   g_srcs[ETOT];
__device__ float g_sums[GG * CH2];
__device__ int   g_cnt[GG];

// ---------------- CSR build ----------------
__global__ void k_degree(const int* __restrict__ ei) {
    int e = blockIdx.x * blockDim.x + threadIdx.x;
    if (e >= ETOT) return;
    int dst = (e < EE) ? ei[EE + e] : (e - EE);
    atomicAdd(&g_deg[dst], 1);
}

__global__ void k_scan1() {
    __shared__ int sh[SCB];
    int i = blockIdx.x * SCB + threadIdx.x;
    int v = (i < NN) ? g_deg[i] : 0;
    sh[threadIdx.x] = v;
    __syncthreads();
    for (int off = 1; off < SCB; off <<= 1) {
        int t = (threadIdx.x >= off) ? sh[threadIdx.x - off] : 0;
        __syncthreads();
        sh[threadIdx.x] += t;
        __syncthreads();
    }
    if (i < NN) g_incl[i] = sh[threadIdx.x];
    if (threadIdx.x == SCB - 1) g_part[blockIdx.x] = sh[threadIdx.x];
}

__global__ void k_scan2(int nb) {
    __shared__ int sh[64];
    int v = (threadIdx.x < nb) ? g_part[threadIdx.x] : 0;
    sh[threadIdx.x] = v;
    __syncthreads();
    for (int off = 1; off < 64; off <<= 1) {
        int t = (threadIdx.x >= off) ? sh[threadIdx.x - off] : 0;
        __syncthreads();
        sh[threadIdx.x] += t;
        __syncthreads();
    }
    g_part[threadIdx.x] = sh[threadIdx.x] - v;  // exclusive prefix of block totals
}

__global__ void k_scan3() {
    int i = blockIdx.x * SCB + threadIdx.x;
    if (i < NN) {
        int excl = g_incl[i] - g_deg[i] + g_part[blockIdx.x];
        g_off[i]  = excl;
        g_wcur[i] = excl;
    }
    if (i == 0) g_off[NN] = ETOT;
}

__global__ void k_scatter(const int* __restrict__ ei) {
    int e = blockIdx.x * blockDim.x + threadIdx.x;
    if (e >= ETOT) return;
    int src, dst;
    if (e < EE) { src = ei[e]; dst = ei[EE + e]; }
    else        { src = e - EE; dst = src; }
    int pos = atomicAdd(&g_wcur[dst], 1);
    g_srcs[pos] = src;
}

// ---------------- dual-weight fp32 GEMM: C[M, 2N], left half A@W0+b0, right A@W1+b1 ----
// BM=BN=128, BK=8, 256 threads, 8x8 micro-tile per thread (split 4+4 at offset 64)
__global__ __launch_bounds__(256) void gemm_dual(
    const float* __restrict__ A,
    const float* __restrict__ W0, const float* __restrict__ W1,
    const float* __restrict__ b0, const float* __restrict__ b1,
    float* __restrict__ C, int M, int K, int N) {
    __shared__ float As[8][128];
    __shared__ float Ws[8][128];
    int tid = threadIdx.x;
    int tx = tid & 15, ty = tid >> 4;
    int rowBase = blockIdx.y * 128;
    int colBase = blockIdx.x * 128;          // in [0, 2N)
    const float* W    = (colBase < N) ? W0 : W1;
    const float* bias = (colBase < N) ? b0 : b1;
    int cb = (colBase < N) ? colBase : colBase - N;

    float acc[8][8];
#pragma unroll
    for (int i = 0; i < 8; i++)
#pragma unroll
        for (int j = 0; j < 8; j++) acc[i][j] = 0.f;

    int ar = tid >> 1, akb = (tid & 1) * 4;
    int wk = tid >> 5, wc = (tid & 31) * 4;

    for (int k0 = 0; k0 < K; k0 += 8) {
#pragma unroll
        for (int j = 0; j < 4; j++) {
            int gk = k0 + akb + j;
            int gr = rowBase + ar;
            As[akb + j][ar] = (gr < M && gk < K) ? A[(long)gr * K + gk] : 0.f;
        }
        if (k0 + wk < K) {
            *(float4*)&Ws[wk][wc] =
                *(const float4*)&W[(long)(k0 + wk) * N + cb + wc];
        } else {
            Ws[wk][wc] = 0.f; Ws[wk][wc + 1] = 0.f;
            Ws[wk][wc + 2] = 0.f; Ws[wk][wc + 3] = 0.f;
        }
        __syncthreads();
#pragma unroll
        for (int kk = 0; kk < 8; kk++) {
            float4 a0 = *(const float4*)&As[kk][ty * 4];
            float4 a1 = *(const float4*)&As[kk][64 + ty * 4];
            float4 w0 = *(const float4*)&Ws[kk][tx * 4];
            float4 w1 = *(const float4*)&Ws[kk][64 + tx * 4];
            float a[8] = {a0.x, a0.y, a0.z, a0.w, a1.x, a1.y, a1.z, a1.w};
            float w[8] = {w0.x, w0.y, w0.z, w0.w, w1.x, w1.y, w1.z, w1.w};
#pragma unroll
            for (int i = 0; i < 8; i++)
#pragma unroll
                for (int j = 0; j < 8; j++) acc[i][j] += a[i] * w[j];
        }
        __syncthreads();
    }
    float4 bv0 = *(const float4*)&bias[cb + tx * 4];
    float4 bv1 = *(const float4*)&bias[cb + 64 + tx * 4];
    float bb[8] = {bv0.x, bv0.y, bv0.z, bv0.w, bv1.x, bv1.y, bv1.z, bv1.w};
    long ldc = 2L * N;
#pragma unroll
    for (int i = 0; i < 8; i++) {
        int r = rowBase + ((i < 4) ? (ty * 4 + i) : (64 + ty * 4 + (i - 4)));
        if (r >= M) continue;
        float4 o0 = make_float4(acc[i][0] + bb[0], acc[i][1] + bb[1],
                                acc[i][2] + bb[2], acc[i][3] + bb[3]);
        float4 o1 = make_float4(acc[i][4] + bb[4], acc[i][5] + bb[5],
                                acc[i][6] + bb[6], acc[i][7] + bb[7]);
        *(float4*)&C[r * ldc + colBase + tx * 4] = o0;
        *(float4*)&C[r * ldc + colBase + 64 + tx * 4] = o1;
    }
}

// ---------------- GATv2 layer: warp-per-dst-node, single edge pass, no-max softmax --
// xlr layout: row d holds [xl (CH floats) | xr (CH floats)].
// Flat channel f=4*(lane+32v)+{0..3}; head = (lane+32v)/16 for H=4,C=64.
// After xor-reduce over {1,2,4,8}, each 16-lane group holds its head's logit.
template <int HEADS, int CH>
__global__ __launch_bounds__(256) void gat_kernel(
    const float4* __restrict__ xlr4, const float4* __restrict__ att4,
    const float4* __restrict__ bias4, float4* __restrict__ out4) {
    constexpr int V   = CH / 128;
    constexpr int C4  = CH / 4;
    constexpr int ROW = 2 * C4;
    int gw   = (blockIdx.x * blockDim.x + threadIdx.x) >> 5;
    int lane = threadIdx.x & 31;
    if (gw >= NN) return;
    const int d = gw;

    float4 xr[V], at[V];
#pragma unroll
    for (int v = 0; v < V; v++) {
        xr[v] = xlr4[(long)d * ROW + C4 + lane + 32 * v];
        at[v] = att4[lane + 32 * v];
    }
    float den[V];
    float4 acc[V];
#pragma unroll
    for (int v = 0; v < V; v++) {
        den[v] = 0.f;
        acc[v] = make_float4(0.f, 0.f, 0.f, 0.f);
    }

    int beg = g_off[d], end = g_off[d + 1];  // end > beg (self-loop guaranteed)
    int s = g_srcs[beg];
    float4 xn[V];
#pragma unroll
    for (int v = 0; v < V; v++) xn[v] = xlr4[(long)s * ROW + lane + 32 * v];

    for (int i = beg; i < end; i++) {
        float4 xc[V];
#pragma unroll
        for (int v = 0; v < V; v++) xc[v] = xn[v];
        if (i + 1 < end) {
            int s2 = g_srcs[i + 1];
#pragma unroll
            for (int v = 0; v < V; v++) xn[v] = xlr4[(long)s2 * ROW + lane + 32 * v];
        }
        float part[V];
#pragma unroll
        for (int v = 0; v < V; v++) {
            float4 x = xc[v], r = xr[v], a = at[v];
            float t, p;
            t = x.x + r.x; t = fmaxf(t, 0.f) + 0.2f * fminf(t, 0.f); p  = t * a.x;
            t = x.y + r.y; t = fmaxf(t, 0.f) + 0.2f * fminf(t, 0.f); p += t * a.y;
            t = x.z + r.z; t = fmaxf(t, 0.f) + 0.2f * fminf(t, 0.f); p += t * a.z;
            t = x.w + r.w; t = fmaxf(t, 0.f) + 0.2f * fminf(t, 0.f); p += t * a.w;
            part[v] = p;
        }
        float w[V];
        if constexpr (HEADS == 1) {
            float p = part[0];
#pragma unroll
            for (int o = 16; o > 0; o >>= 1) p += __shfl_xor_sync(0xffffffffu, p, o);
            w[0] = __expf(p);
        } else {
#pragma unroll
            for (int v = 0; v < V; v++) {
                float p = part[v];
                p += __shfl_xor_sync(0xffffffffu, p, 1);
                p += __shfl_xor_sync(0xffffffffu, p, 2);
                p += __shfl_xor_sync(0xffffffffu, p, 4);
                p += __shfl_xor_sync(0xffffffffu, p, 8);
                w[v] = __expf(p);  // each 16-lane group has its own head's logit
            }
        }
#pragma unroll
        for (int v = 0; v < V; v++) {
            den[v] += w[v];
            acc[v].x += w[v] * xc[v].x;
            acc[v].y += w[v] * xc[v].y;
            acc[v].z += w[v] * xc[v].z;
            acc[v].w += w[v] * xc[v].w;
        }
    }
#pragma unroll
    for (int v = 0; v < V; v++) {
        float inv = 1.f / (den[v] + 1e-16f);
        float4 b = bias4[lane + 32 * v];
        float4 o;
        o.x = fmaxf(acc[v].x * inv + b.x, 0.f);
        o.y = fmaxf(acc[v].y * inv + b.y, 0.f);
        o.z = fmaxf(acc[v].z * inv + b.z, 0.f);
        o.w = fmaxf(acc[v].w * inv + b.w, 0.f);
        out4[(long)d * C4 + lane + 32 * v] = o;
    }
}

// ---------------- global mean pool ----------------
__global__ void k_pool(const float* __restrict__ h2, const int* __restrict__ batch) {
    int t = blockIdx.x * blockDim.x + threadIdx.x;
    int w = t >> 5, lane = t & 31;
    if (w >= NN) return;
    int g = batch[w];
#pragma unroll
    for (int c = 0; c < CH2 / 32; c++)
        atomicAdd(&g_sums[g * CH2 + lane + 32 * c], h2[(long)w * CH2 + lane + 32 * c]);
    if (lane == 0) atomicAdd(&g_cnt[g], 1);
}

__global__ void k_final(float* __restrict__ out) {
    int i = blockIdx.x * blockDim.x + threadIdx.x;
    if (i < GG * CH2) {
        int g = i / CH2;
        float c = (float)g_cnt[g];
        out[i] = g_sums[i] / fmaxf(c, 1.f);
    }
}

// Restore zero invariant for the next replay (statics start zeroed at load).
__global__ void k_reset() {
    int i = blockIdx.x * blockDim.x + threadIdx.x;
    if (i < NN) g_deg[i] = 0;
    if (i < GG * CH2) g_sums[i] = 0.f;
    if (i < GG) g_cnt[i] = 0;
}

// ---------------- launch ----------------
extern "C" void kernel_launch(void* const* d_in, const int* in_sizes, int n_in,
                              void* d_out, int out_size) {
    const float* x     = (const float*)d_in[0];
    const int*   ei    = (const int*)d_in[1];
    const int*   batch = (const int*)d_in[2];
    const float* Wl1   = (const float*)d_in[3];
    const float* bl1   = (const float*)d_in[4];
    const float* Wr1   = (const float*)d_in[5];
    const float* br1   = (const float*)d_in[6];
    const float* att1  = (const float*)d_in[7];
    const float* bias1 = (const float*)d_in[8];
    const float* Wl2   = (const float*)d_in[9];
    const float* bl2   = (const float*)d_in[10];
    const float* Wr2   = (const float*)d_in[11];
    const float* br2   = (const float*)d_in[12];
    const float* att2  = (const float*)d_in[13];
    const float* bias2 = (const float*)d_in[14];

    float *xlr1, *h1, *xlr2, *h2;
    cudaGetSymbolAddress((void**)&xlr1, g_xlr1);
    cudaGetSymbolAddress((void**)&h1,   g_h1);
    cudaGetSymbolAddress((void**)&xlr2, g_xlr2);
    cudaGetSymbolAddress((void**)&h2,   g_h2);

    int nb = (NN + SCB - 1) / SCB;

    k_degree<<<(ETOT + 255) / 256, 256>>>(ei);       // #1
    k_scan1<<<nb, SCB>>>();                          // #2
    k_scan2<<<1, 64>>>(nb);                          // #3
    k_scan3<<<nb, SCB>>>();                          // #4
    k_scatter<<<(ETOT + 255) / 256, 256>>>(ei);      // #5

    dim3 g1(2 * CH1 / 128, (NN + 127) / 128);
    gemm_dual<<<g1, 256>>>(x, Wl1, Wr1, bl1, br1, xlr1, NN, KIN, CH1);   // #6 (profiled)

    gat_kernel<4, 256><<<(NN + 7) / 8, 256>>>(
        (const float4*)xlr1, (const float4*)att1, (const float4*)bias1,
        (float4*)h1);                                                     // #7

    dim3 g2(2 * CH2 / 128, (NN + 127) / 128);
    gemm_dual<<<g2, 256>>>(h1, Wl2, Wr2, bl2, br2, xlr2, NN, CH1, CH2);  // #8

    gat_kernel<1, 128><<<(NN + 7) / 8, 256>>>(
        (const float4*)xlr2, (const float4*)att2, (const float4*)bias2,
        (float4*)h2);                                                     // #9

    k_pool<<<(NN * 32 + 255) / 256, 256>>>(h2, batch);                   // #10
    k_final<<<(GG * CH2 + 255) / 256, 256>>>((float*)d_out);             // #11
    k_reset<<<(NN + 255) / 256, 256>>>();                                // #12
}

// round 3
// speedup vs baseline: 1.7797x; 1.4193x over previous
#include <cuda_runtime.h>
#include <cstdint>

#define NN   50000
#define EE   800000
#define ETOT (EE + NN)
#define GG   128
#define KIN  38
#define CH1  256
#define CH2  128
#define SCB  1024

// ---------------- static device scratch ----------------
__device__ float g_xlr1[NN * 2 * CH1];
__device__ float g_h1  [NN * CH1];
__device__ float g_xlr2[NN * 2 * CH2];
__device__ float g_h2  [NN * CH2];
__device__ int   g_deg[NN];
__device__ int   g_incl[NN];
__device__ int   g_off[NN + 1];
__device__ int   g_wcur[NN];
__device__ int   g_part[64];
__device__ int   g_srcs[ETOT];
__device__ float g_sums[GG * CH2];
__device__ int   g_cnt[GG];

// ---------------- CSR build ----------------
__global__ void k_degree(const int* __restrict__ ei) {
    int e = blockIdx.x * blockDim.x + threadIdx.x;
    if (e >= ETOT) return;
    int dst = (e < EE) ? ei[EE + e] : (e - EE);
    atomicAdd(&g_deg[dst], 1);
}

__global__ void k_scan1() {
    __shared__ int sh[SCB];
    int i = blockIdx.x * SCB + threadIdx.x;
    int v = (i < NN) ? g_deg[i] : 0;
    sh[threadIdx.x] = v;
    __syncthreads();
    for (int off = 1; off < SCB; off <<= 1) {
        int t = (threadIdx.x >= off) ? sh[threadIdx.x - off] : 0;
        __syncthreads();
        sh[threadIdx.x] += t;
        __syncthreads();
    }
    if (i < NN) g_incl[i] = sh[threadIdx.x];
    if (threadIdx.x == SCB - 1) g_part[blockIdx.x] = sh[threadIdx.x];
}

__global__ void k_scan2(int nb) {
    __shared__ int sh[64];
    int v = (threadIdx.x < nb) ? g_part[threadIdx.x] : 0;
    sh[threadIdx.x] = v;
    __syncthreads();
    for (int off = 1; off < 64; off <<= 1) {
        int t = (threadIdx.x >= off) ? sh[threadIdx.x - off] : 0;
        __syncthreads();
        sh[threadIdx.x] += t;
        __syncthreads();
    }
    g_part[threadIdx.x] = sh[threadIdx.x] - v;
}

__global__ void k_scan3() {
    int i = blockIdx.x * SCB + threadIdx.x;
    if (i < NN) {
        int excl = g_incl[i] - g_deg[i] + g_part[blockIdx.x];
        g_off[i]  = excl;
        g_wcur[i] = excl;
    }
    if (i == 0) g_off[NN] = ETOT;
}

__global__ void k_scatter(const int* __restrict__ ei) {
    int e = blockIdx.x * blockDim.x + threadIdx.x;
    if (e >= ETOT) return;
    int src, dst;
    if (e < EE) { src = ei[e]; dst = ei[EE + e]; }
    else        { src = e - EE; dst = src; }
    int pos = atomicAdd(&g_wcur[dst], 1);
    g_srcs[pos] = src;
}

// ---------------- tf32 tensor-core dual GEMM ----------------
// C[M, 2N]: cols [0,N) = A@W0+b0, [N,2N) = A@W1+b1.
// BM=128, BN=128, BK=16. 256 threads = 8 warps as 4(m) x 2(n).
// Warp tile 32x64 = 2 x 8 m16n8k8 tf32 mmas per k-step.
__device__ __forceinline__ uint32_t f2tf32(float f) {
    uint32_t u;
    asm("cvt.rna.tf32.f32 %0, %1;" : "=r"(u) : "f"(f));
    return u;
}

#define MMA_TF32(d, a, b)                                                \
    asm volatile(                                                        \
        "mma.sync.aligned.m16n8k8.row.col.f32.tf32.tf32.f32 "            \
        "{%0,%1,%2,%3}, {%4,%5,%6,%7}, {%8,%9}, {%0,%1,%2,%3};"          \
        : "+f"(d[0]), "+f"(d[1]), "+f"(d[2]), "+f"(d[3])                 \
        : "r"(a[0]), "r"(a[1]), "r"(a[2]), "r"(a[3]), "r"(b[0]), "r"(b[1]))

__global__ __launch_bounds__(256) void gemm_tf32_dual(
    const float* __restrict__ A,
    const float* __restrict__ W0, const float* __restrict__ W1,
    const float* __restrict__ b0, const float* __restrict__ b1,
    float* __restrict__ C, int M, int K, int N) {
    __shared__ uint32_t As[128 * 20];   // [m][k], stride 20 (conflict-free)
    __shared__ uint32_t Bs[16 * 136];   // [k][n], stride 136 (conflict-free)

    int tid  = threadIdx.x;
    int lane = tid & 31;
    int wid  = tid >> 5;
    int wm = wid & 3;          // m-warp 0..3 (32 rows each)
    int wn = wid >> 2;         // n-warp 0..1 (64 cols each)
    int l4 = lane >> 2;        // 0..7
    int lq = lane & 3;         // 0..3

    int rowBase = blockIdx.y * 128;
    int colBase = blockIdx.x * 128;          // in [0, 2N)
    const float* W    = (colBase < N) ? W0 : W1;
    const float* bias = (colBase < N) ? b0 : b1;
    int cb = (colBase < N) ? colBase : colBase - N;

    float c[2][8][4];
#pragma unroll
    for (int mt = 0; mt < 2; mt++)
#pragma unroll
        for (int nt = 0; nt < 8; nt++)
#pragma unroll
            for (int r = 0; r < 4; r++) c[mt][nt][r] = 0.f;

    for (int k0 = 0; k0 < K; k0 += 16) {
        // load A tile (128 x 16)
#pragma unroll
        for (int i = 0; i < 8; i++) {
            int lin = i * 256 + tid;
            int m = lin >> 4, k = lin & 15;
            int gr = rowBase + m, gk = k0 + k;
            float v = (gr < M && gk < K) ? A[(long)gr * K + gk] : 0.f;
            As[m * 20 + k] = f2tf32(v);
        }
        // load B tile (16 x 128)
#pragma unroll
        for (int i = 0; i < 8; i++) {
            int lin = i * 256 + tid;
            int k = lin >> 7, n = lin & 127;
            int gk = k0 + k;
            float v = (gk < K) ? W[(long)gk * N + cb + n] : 0.f;
            Bs[k * 136 + n] = f2tf32(v);
        }
        __syncthreads();

#pragma unroll
        for (int ks = 0; ks < 2; ks++) {
            int kb = ks * 8;
            uint32_t a[2][4];
#pragma unroll
            for (int mt = 0; mt < 2; mt++) {
                int r = wm * 32 + mt * 16 + l4;
                a[mt][0] = As[r * 20 + kb + lq];
                a[mt][1] = As[(r + 8) * 20 + kb + lq];
                a[mt][2] = As[r * 20 + kb + lq + 4];
                a[mt][3] = As[(r + 8) * 20 + kb + lq + 4];
            }
            uint32_t b[8][2];
#pragma unroll
            for (int nt = 0; nt < 8; nt++) {
                int n = wn * 64 + nt * 8 + l4;
                b[nt][0] = Bs[(kb + lq) * 136 + n];
                b[nt][1] = Bs[(kb + lq + 4) * 136 + n];
            }
#pragma unroll
            for (int mt = 0; mt < 2; mt++)
#pragma unroll
                for (int nt = 0; nt < 8; nt++)
                    MMA_TF32(c[mt][nt], a[mt], b[nt]);
        }
        __syncthreads();
    }

    long ldc = 2L * N;
#pragma unroll
    for (int mt = 0; mt < 2; mt++) {
        int r0 = rowBase + wm * 32 + mt * 16 + l4;
#pragma unroll
        for (int nt = 0; nt < 8; nt++) {
            int colLoc = wn * 64 + nt * 8 + 2 * lq;   // within 128-col block
            float bv0 = bias[cb + colLoc];
            float bv1 = bias[cb + colLoc + 1];
            int gc = colBase + colLoc;
            if (r0 < M) {
                float2 o = make_float2(c[mt][nt][0] + bv0, c[mt][nt][1] + bv1);
                *(float2*)&C[(long)r0 * ldc + gc] = o;
            }
            if (r0 + 8 < M) {
                float2 o = make_float2(c[mt][nt][2] + bv0, c[mt][nt][3] + bv1);
                *(float2*)&C[(long)(r0 + 8) * ldc + gc] = o;
            }
        }
    }
}

// ---------------- GATv2 layer: warp-per-dst-node, single edge pass, no-max softmax --
template <int HEADS, int CH>
__global__ __launch_bounds__(256) void gat_kernel(
    const float4* __restrict__ xlr4, const float4* __restrict__ att4,
    const float4* __restrict__ bias4, float4* __restrict__ out4) {
    constexpr int V   = CH / 128;
    constexpr int C4  = CH / 4;
    constexpr int ROW = 2 * C4;
    int gw   = (blockIdx.x * blockDim.x + threadIdx.x) >> 5;
    int lane = threadIdx.x & 31;
    if (gw >= NN) return;
    const int d = gw;

    float4 xr[V], at[V];
#pragma unroll
    for (int v = 0; v < V; v++) {
        xr[v] = xlr4[(long)d * ROW + C4 + lane + 32 * v];
        at[v] = att4[lane + 32 * v];
    }
    float den[V];
    float4 acc[V];
#pragma unroll
    for (int v = 0; v < V; v++) {
        den[v] = 0.f;
        acc[v] = make_float4(0.f, 0.f, 0.f, 0.f);
    }

    int beg = g_off[d], end = g_off[d + 1];
    int s = g_srcs[beg];
    float4 xn[V];
#pragma unroll
    for (int v = 0; v < V; v++) xn[v] = xlr4[(long)s * ROW + lane + 32 * v];

    for (int i = beg; i < end; i++) {
        float4 xc[V];
#pragma unroll
        for (int v = 0; v < V; v++) xc[v] = xn[v];
        if (i + 1 < end) {
            int s2 = g_srcs[i + 1];
#pragma unroll
            for (int v = 0; v < V; v++) xn[v] = xlr4[(long)s2 * ROW + lane + 32 * v];
        }
        float part[V];
#pragma unroll
        for (int v = 0; v < V; v++) {
            float4 x = xc[v], r = xr[v], a = at[v];
            float t, p;
            t = x.x + r.x; t = fmaxf(t, 0.f) + 0.2f * fminf(t, 0.f); p  = t * a.x;
            t = x.y + r.y; t = fmaxf(t, 0.f) + 0.2f * fminf(t, 0.f); p += t * a.y;
            t = x.z + r.z; t = fmaxf(t, 0.f) + 0.2f * fminf(t, 0.f); p += t * a.z;
            t = x.w + r.w; t = fmaxf(t, 0.f) + 0.2f * fminf(t, 0.f); p += t * a.w;
            part[v] = p;
        }
        float w[V];
        if constexpr (HEADS == 1) {
            float p = part[0];
#pragma unroll
            for (int o = 16; o > 0; o >>= 1) p += __shfl_xor_sync(0xffffffffu, p, o);
            w[0] = __expf(p);
        } else {
#pragma unroll
            for (int v = 0; v < V; v++) {
                float p = part[v];
                p += __shfl_xor_sync(0xffffffffu, p, 1);
                p += __shfl_xor_sync(0xffffffffu, p, 2);
                p += __shfl_xor_sync(0xffffffffu, p, 4);
                p += __shfl_xor_sync(0xffffffffu, p, 8);
                w[v] = __expf(p);
            }
        }
#pragma unroll
        for (int v = 0; v < V; v++) {
            den[v] += w[v];
            acc[v].x += w[v] * xc[v].x;
            acc[v].y += w[v] * xc[v].y;
            acc[v].z += w[v] * xc[v].z;
            acc[v].w += w[v] * xc[v].w;
        }
    }
#pragma unroll
    for (int v = 0; v < V; v++) {
        float inv = 1.f / (den[v] + 1e-16f);
        float4 b = bias4[lane + 32 * v];
        float4 o;
        o.x = fmaxf(acc[v].x * inv + b.x, 0.f);
        o.y = fmaxf(acc[v].y * inv + b.y, 0.f);
        o.z = fmaxf(acc[v].z * inv + b.z, 0.f);
        o.w = fmaxf(acc[v].w * inv + b.w, 0.f);
        out4[(long)d * C4 + lane + 32 * v] = o;
    }
}

// ---------------- global mean pool ----------------
__global__ void k_pool(const float* __restrict__ h2, const int* __restrict__ batch) {
    int t = blockIdx.x * blockDim.x + threadIdx.x;
    int w = t >> 5, lane = t & 31;
    if (w >= NN) return;
    int g = batch[w];
#pragma unroll
    for (int c = 0; c < CH2 / 32; c++)
        atomicAdd(&g_sums[g * CH2 + lane + 32 * c], h2[(long)w * CH2 + lane + 32 * c]);
    if (lane == 0) atomicAdd(&g_cnt[g], 1);
}

__global__ void k_final(float* __restrict__ out) {
    int i = blockIdx.x * blockDim.x + threadIdx.x;
    if (i < GG * CH2) {
        int g = i / CH2;
        float c = (float)g_cnt[g];
        out[i] = g_sums[i] / fmaxf(c, 1.f);
    }
}

__global__ void k_reset() {
    int i = blockIdx.x * blockDim.x + threadIdx.x;
    if (i < NN) g_deg[i] = 0;
    if (i < GG * CH2) g_sums[i] = 0.f;
    if (i < GG) g_cnt[i] = 0;
}

// ---------------- launch ----------------
extern "C" void kernel_launch(void* const* d_in, const int* in_sizes, int n_in,
                              void* d_out, int out_size) {
    const float* x     = (const float*)d_in[0];
    const int*   ei    = (const int*)d_in[1];
    const int*   batch = (const int*)d_in[2];
    const float* Wl1   = (const float*)d_in[3];
    const float* bl1   = (const float*)d_in[4];
    const float* Wr1   = (const float*)d_in[5];
    const float* br1   = (const float*)d_in[6];
    const float* att1  = (const float*)d_in[7];
    const float* bias1 = (const float*)d_in[8];
    const float* Wl2   = (const float*)d_in[9];
    const float* bl2   = (const float*)d_in[10];
    const float* Wr2   = (const float*)d_in[11];
    const float* br2   = (const float*)d_in[12];
    const float* att2  = (const float*)d_in[13];
    const float* bias2 = (const float*)d_in[14];

    float *xlr1, *h1, *xlr2, *h2;
    cudaGetSymbolAddress((void**)&xlr1, g_xlr1);
    cudaGetSymbolAddress((void**)&h1,   g_h1);
    cudaGetSymbolAddress((void**)&xlr2, g_xlr2);
    cudaGetSymbolAddress((void**)&h2,   g_h2);

    int nb = (NN + SCB - 1) / SCB;

    k_degree<<<(ETOT + 255) / 256, 256>>>(ei);       // #1
    k_scan1<<<nb, SCB>>>();                          // #2
    k_scan2<<<1, 64>>>(nb);                          // #3

    dim3 g1(2 * CH1 / 128, (NN + 127) / 128);
    gemm_tf32_dual<<<g1, 256>>>(x, Wl1, Wr1, bl1, br1, xlr1, NN, KIN, CH1);  // #4 (profiled)

    k_scan3<<<nb, SCB>>>();                          // #5
    k_scatter<<<(ETOT + 255) / 256, 256>>>(ei);      // #6

    gat_kernel<4, 256><<<(NN + 7) / 8, 256>>>(
        (const float4*)xlr1, (const float4*)att1, (const float4*)bias1,
        (float4*)h1);                                                         // #7

    dim3 g2(2 * CH2 / 128, (NN + 127) / 128);
    gemm_tf32_dual<<<g2, 256>>>(h1, Wl2, Wr2, bl2, br2, xlr2, NN, CH1, CH2); // #8

    gat_kernel<1, 128><<<(NN + 7) / 8, 256>>>(
        (const float4*)xlr2, (const float4*)att2, (const float4*)bias2,
        (float4*)h2);                                                         // #9

    k_pool<<<(NN * 32 + 255) / 256, 256>>>(h2, batch);                       // #10
    k_final<<<(GG * CH2 + 255) / 256, 256>>>((float*)d_out);                 // #11
    k_reset<<<(NN + 255) / 256, 256>>>();                                    // #12
}

// round 4
// speedup vs baseline: 1.8728x; 1.0523x over previous
#include <cuda_runtime.h>
#include <cuda_fp16.h>
#include <cstdint>

#define NN   50000
#define NNP  50048            // 391 * 128 (padded rows)
#define EE   800000
#define ETOT (EE + NN)
#define GG   128
#define KIN  38
#define CH1  256
#define CH2  128
#define SCB  1024

// ---------------- static device scratch ----------------
__device__ float  g_xpad[NNP * 40];       // tf32-rounded, K padded 38->40
__device__ float  g_w1t [40 * 512];       // tf32 [Wl1|Wr1], rows 38,39 zero
__device__ float  g_w2t [256 * 256];      // tf32 [Wl2|Wr2]
__device__ __half g_xl1h[NN * CH1];
__device__ float  g_xr1 [NN * CH1];
__device__ float  g_h1  [NNP * CH1];      // tf32-rounded; tail rows stay 0
__device__ __half g_xl2h[NN * CH2];
__device__ float  g_xr2 [NN * CH2];
__device__ float  g_h2  [NN * CH2];
__device__ int    g_deg[NN];
__device__ int    g_incl[NN];
__device__ int    g_off[NN + 1];
__device__ int    g_wcur[NN];
__device__ int    g_part[64];
__device__ int    g_srcs[ETOT];
__device__ float  g_sums[GG * CH2];
__device__ int    g_cnt[GG];

__device__ __forceinline__ uint32_t f2tf32(float f) {
    uint32_t u;
    asm("cvt.rna.tf32.f32 %0, %1;" : "=r"(u) : "f"(f));
    return u;
}

// ---------------- prep: tf32-round inputs/weights into padded layouts ------
__global__ void k_prep_x(const float* __restrict__ x) {
    int i = blockIdx.x * blockDim.x + threadIdx.x;
    if (i >= NNP * 40) return;
    int r = i / 40, c = i - r * 40;
    float v = (r < NN && c < KIN) ? x[r * KIN + c] : 0.f;
    g_xpad[i] = __uint_as_float(f2tf32(v));
}

__global__ void k_prep_w1(const float* __restrict__ Wl, const float* __restrict__ Wr) {
    int i = blockIdx.x * blockDim.x + threadIdx.x;
    if (i >= 40 * 512) return;
    int r = i >> 9, c = i & 511;
    float v = 0.f;
    if (r < KIN) v = (c < 256) ? Wl[r * 256 + c] : Wr[r * 256 + (c - 256)];
    g_w1t[i] = __uint_as_float(f2tf32(v));
}

__global__ void k_prep_w2(const float* __restrict__ Wl, const float* __restrict__ Wr) {
    int i = blockIdx.x * blockDim.x + threadIdx.x;
    if (i >= 256 * 256) return;
    int r = i >> 8, c = i & 255;
    float v = (c < 128) ? Wl[r * 128 + c] : Wr[r * 128 + (c - 128)];
    g_w2t[i] = __uint_as_float(f2tf32(v));
}

// ---------------- CSR build ----------------
__global__ void k_degree(const int* __restrict__ ei) {
    int e = blockIdx.x * blockDim.x + threadIdx.x;
    if (e >= ETOT) return;
    int dst = (e < EE) ? ei[EE + e] : (e - EE);
    atomicAdd(&g_deg[dst], 1);
}

__global__ void k_scan1() {
    __shared__ int sh[SCB];
    int i = blockIdx.x * SCB + threadIdx.x;
    int v = (i < NN) ? g_deg[i] : 0;
    sh[threadIdx.x] = v;
    __syncthreads();
    for (int off = 1; off < SCB; off <<= 1) {
        int t = (threadIdx.x >= off) ? sh[threadIdx.x - off] : 0;
        __syncthreads();
        sh[threadIdx.x] += t;
        __syncthreads();
    }
    if (i < NN) g_incl[i] = sh[threadIdx.x];
    if (threadIdx.x == SCB - 1) g_part[blockIdx.x] = sh[threadIdx.x];
}

__global__ void k_scan2(int nb) {
    __shared__ int sh[64];
    int v = (threadIdx.x < nb) ? g_part[threadIdx.x] : 0;
    sh[threadIdx.x] = v;
    __syncthreads();
    for (int off = 1; off < 64; off <<= 1) {
        int t = (threadIdx.x >= off) ? sh[threadIdx.x - off] : 0;
        __syncthreads();
        sh[threadIdx.x] += t;
        __syncthreads();
    }
    g_part[threadIdx.x] = sh[threadIdx.x] - v;
}

__global__ void k_scan3() {
    int i = blockIdx.x * SCB + threadIdx.x;
    if (i < NN) {
        int excl = g_incl[i] - g_deg[i] + g_part[blockIdx.x];
        g_off[i]  = excl;
        g_wcur[i] = excl;
    }
    if (i == 0) g_off[NN] = ETOT;
}

__global__ void k_scatter(const int* __restrict__ ei) {
    int e = blockIdx.x * blockDim.x + threadIdx.x;
    if (e >= ETOT) return;
    int src, dst;
    if (e < EE) { src = ei[e]; dst = ei[EE + e]; }
    else        { src = e - EE; dst = src; }
    int pos = atomicAdd(&g_wcur[dst], 1);
    g_srcs[pos] = src;
}

// ---------------- tf32 tensor-core GEMM (cp.async, no cvt) ----------------
#define MMA_TF32(d, a, b)                                                \
    asm volatile(                                                        \
        "mma.sync.aligned.m16n8k8.row.col.f32.tf32.tf32.f32 "            \
        "{%0,%1,%2,%3}, {%4,%5,%6,%7}, {%8,%9}, {%0,%1,%2,%3};"          \
        : "+f"(d[0]), "+f"(d[1]), "+f"(d[2]), "+f"(d[3])                 \
        : "r"(a[0]), "r"(a[1]), "r"(a[2]), "r"(a[3]), "r"(b[0]), "r"(b[1]))

template <int BK, int PA>
__device__ __forceinline__ void load_tile_async(
    float* As, float* Bs, const float* __restrict__ A, int lda,
    const float* __restrict__ Wt, int ldw, int rowBase, int colBase,
    int it, int tid) {
    constexpr int ACH = 128 * BK / 4;
    const float* Ab = A + (long)rowBase * lda + it * BK;
#pragma unroll
    for (int c = tid; c < ACH; c += 256) {
        int row = c / (BK / 4), kc = c - row * (BK / 4);
        uint32_t dst = (uint32_t)__cvta_generic_to_shared(As + row * PA + kc * 4);
        const float* src = Ab + (long)row * lda + kc * 4;
        asm volatile("cp.async.ca.shared.global [%0], [%1], 16;"
                     :: "r"(dst), "l"(src) : "memory");
    }
    constexpr int BCH = BK * 32;
    const float* Bb = Wt + (long)it * BK * ldw + colBase;
#pragma unroll
    for (int c = tid; c < BCH; c += 256) {
        int k = c >> 5, nc = c & 31;
        uint32_t dst = (uint32_t)__cvta_generic_to_shared(Bs + k * 136 + nc * 4);
        const float* src = Bb + (long)k * ldw + nc * 4;
        asm volatile("cp.async.ca.shared.global [%0], [%1], 16;"
                     :: "r"(dst), "l"(src) : "memory");
    }
    asm volatile("cp.async.commit_group;" ::: "memory");
}

// C[M, 2N]: cols [0,N) -> Cl (half), [N,2N) -> Cr (float). A is padded/tf32.
template <int BK, int PA, int NITER>
__global__ __launch_bounds__(256) void gemm_tc(
    const float* __restrict__ A, int lda,
    const float* __restrict__ Wt, int ldw,
    const float* __restrict__ b0v, const float* __restrict__ b1v,
    __half* __restrict__ Cl, float* __restrict__ Cr, int N, int M) {
    constexpr int STAGES = (NITER > 1) ? 2 : 1;
    constexpr int KSTEPS = BK / 8;
    __shared__ float As[STAGES][128 * PA];
    __shared__ float Bs[STAGES][BK * 136];

    int tid = threadIdx.x, lane = tid & 31, wid = tid >> 5;
    int wm = wid & 3, wn = wid >> 2, l4 = lane >> 2, lq = lane & 3;
    int rowBase = blockIdx.y * 128;
    int colBase = blockIdx.x * 128;

    float c[2][8][4];
#pragma unroll
    for (int mt = 0; mt < 2; mt++)
#pragma unroll
        for (int nt = 0; nt < 8; nt++)
#pragma unroll
            for (int r = 0; r < 4; r++) c[mt][nt][r] = 0.f;

    load_tile_async<BK, PA>(As[0], Bs[0], A, lda, Wt, ldw, rowBase, colBase, 0, tid);

    for (int it = 0; it < NITER; ++it) {
        int buf = it & (STAGES - 1);
        bool has_next = (STAGES == 2) && (it + 1 < NITER);
        if (has_next)
            load_tile_async<BK, PA>(As[(it + 1) & 1], Bs[(it + 1) & 1],
                                    A, lda, Wt, ldw, rowBase, colBase, it + 1, tid);
        if (has_next) asm volatile("cp.async.wait_group 1;" ::: "memory");
        else          asm volatile("cp.async.wait_group 0;" ::: "memory");
        __syncthreads();
        const float* as = As[buf];
        const float* bs = Bs[buf];
#pragma unroll
        for (int ks = 0; ks < KSTEPS; ks++) {
            int kb = ks * 8;
            uint32_t a[2][4];
#pragma unroll
            for (int mt = 0; mt < 2; mt++) {
                int r = wm * 32 + mt * 16 + l4;
                a[mt][0] = __float_as_uint(as[r * PA + kb + lq]);
                a[mt][1] = __float_as_uint(as[(r + 8) * PA + kb + lq]);
                a[mt][2] = __float_as_uint(as[r * PA + kb + lq + 4]);
                a[mt][3] = __float_as_uint(as[(r + 8) * PA + kb + lq + 4]);
            }
            uint32_t b[8][2];
#pragma unroll
            for (int nt = 0; nt < 8; nt++) {
                int n = wn * 64 + nt * 8 + l4;
                b[nt][0] = __float_as_uint(bs[(kb + lq) * 136 + n]);
                b[nt][1] = __float_as_uint(bs[(kb + lq + 4) * 136 + n]);
            }
#pragma unroll
            for (int mt = 0; mt < 2; mt++)
#pragma unroll
                for (int nt = 0; nt < 8; nt++)
                    MMA_TF32(c[mt][nt], a[mt], b[nt]);
        }
        __syncthreads();
    }

    bool left = colBase < N;
    int cb = left ? colBase : colBase - N;
    const float* bias = left ? b0v : b1v;
#pragma unroll
    for (int mt = 0; mt < 2; mt++) {
        int r0 = rowBase + wm * 32 + mt * 16 + l4;
#pragma unroll
        for (int nt = 0; nt < 8; nt++) {
            int colLoc = wn * 64 + nt * 8 + 2 * lq;
            int gc = cb + colLoc;
            float bv0 = bias[gc], bv1 = bias[gc + 1];
            if (r0 < M) {
                float o0 = c[mt][nt][0] + bv0, o1 = c[mt][nt][1] + bv1;
                if (left) *(__half2*)&Cl[(long)r0 * N + gc] = __floats2half2_rn(o0, o1);
                else      *(float2*)&Cr[(long)r0 * N + gc] = make_float2(o0, o1);
            }
            if (r0 + 8 < M) {
                float o0 = c[mt][nt][2] + bv0, o1 = c[mt][nt][3] + bv1;
                if (left) *(__half2*)&Cl[(long)(r0 + 8) * N + gc] = __floats2half2_rn(o0, o1);
                else      *(float2*)&Cr[(long)(r0 + 8) * N + gc] = make_float2(o0, o1);
            }
        }
    }
}

// ---------------- GATv2: warp-per-dst, fp16 gathered xl, pairwise unroll ----
__device__ __forceinline__ float4 h4tof4(uint2 u) {
    __half2 h0 = *reinterpret_cast<__half2*>(&u.x);
    __half2 h1 = *reinterpret_cast<__half2*>(&u.y);
    float2 a = __half22float2(h0), b = __half22float2(h1);
    return make_float4(a.x, a.y, b.x, b.y);
}

__device__ __forceinline__ float leakydot(float4 f, float4 r, float4 a) {
    float t, p;
    t = f.x + r.x; t = fmaxf(t, 0.f) + 0.2f * fminf(t, 0.f); p  = t * a.x;
    t = f.y + r.y; t = fmaxf(t, 0.f) + 0.2f * fminf(t, 0.f); p += t * a.y;
    t = f.z + r.z; t = fmaxf(t, 0.f) + 0.2f * fminf(t, 0.f); p += t * a.z;
    t = f.w + r.w; t = fmaxf(t, 0.f) + 0.2f * fminf(t, 0.f); p += t * a.w;
    return p;
}

template <int HEADS, int CH, bool ROUND>
__global__ __launch_bounds__(256) void gat_kernel(
    const uint2* __restrict__ xlh, const float4* __restrict__ xr4,
    const float4* __restrict__ att4, const float4* __restrict__ bias4,
    float4* __restrict__ out4) {
    constexpr int V  = CH / 128;
    constexpr int C4 = CH / 4;
    int gw   = (blockIdx.x * blockDim.x + threadIdx.x) >> 5;
    int lane = threadIdx.x & 31;
    if (gw >= NN) return;
    const int d = gw;

    float4 xr[V], at[V];
#pragma unroll
    for (int v = 0; v < V; v++) {
        xr[v] = xr4[(long)d * C4 + lane + 32 * v];
        at[v] = att4[lane + 32 * v];
    }
    float den0[V], den1[V];
    float4 acc0[V], acc1[V];
#pragma unroll
    for (int v = 0; v < V; v++) {
        den0[v] = 0.f; den1[v] = 0.f;
        acc0[v] = make_float4(0.f, 0.f, 0.f, 0.f);
        acc1[v] = make_float4(0.f, 0.f, 0.f, 0.f);
    }

    int beg = g_off[d], end = g_off[d + 1];
    int i = beg;
    for (; i + 2 <= end; i += 2) {
        int s0 = g_srcs[i], s1 = g_srcs[i + 1];
        float4 f0[V], f1[V];
#pragma unroll
        for (int v = 0; v < V; v++) {
            uint2 u0 = xlh[(long)s0 * C4 + lane + 32 * v];
            uint2 u1 = xlh[(long)s1 * C4 + lane + 32 * v];
            f0[v] = h4tof4(u0);
            f1[v] = h4tof4(u1);
        }
        float p0[V], p1[V];
#pragma unroll
        for (int v = 0; v < V; v++) {
            p0[v] = leakydot(f0[v], xr[v], at[v]);
            p1[v] = leakydot(f1[v], xr[v], at[v]);
        }
        float w0[V], w1[V];
        if constexpr (HEADS == 1) {
            float a = p0[0], b = p1[0];
#pragma unroll
            for (int o = 16; o > 0; o >>= 1) {
                a += __shfl_xor_sync(0xffffffffu, a, o);
                b += __shfl_xor_sync(0xffffffffu, b, o);
            }
            w0[0] = __expf(a); w1[0] = __expf(b);
        } else {
#pragma unroll
            for (int v = 0; v < V; v++) {
                float a = p0[v], b = p1[v];
#pragma unroll
                for (int o = 1; o < 16; o <<= 1) {
                    a += __shfl_xor_sync(0xffffffffu, a, o);
                    b += __shfl_xor_sync(0xffffffffu, b, o);
                }
                w0[v] = __expf(a); w1[v] = __expf(b);
            }
        }
#pragma unroll
        for (int v = 0; v < V; v++) {
            den0[v] += w0[v];
            acc0[v].x += w0[v] * f0[v].x; acc0[v].y += w0[v] * f0[v].y;
            acc0[v].z += w0[v] * f0[v].z; acc0[v].w += w0[v] * f0[v].w;
            den1[v] += w1[v];
            acc1[v].x += w1[v] * f1[v].x; acc1[v].y += w1[v] * f1[v].y;
            acc1[v].z += w1[v] * f1[v].z; acc1[v].w += w1[v] * f1[v].w;
        }
    }
    if (i < end) {  // odd tail
        int s0 = g_srcs[i];
        float4 f0[V];
#pragma unroll
        for (int v = 0; v < V; v++) f0[v] = h4tof4(xlh[(long)s0 * C4 + lane + 32 * v]);
        float p0[V];
#pragma unroll
        for (int v = 0; v < V; v++) p0[v] = leakydot(f0[v], xr[v], at[v]);
        float w0[V];
        if constexpr (HEADS == 1) {
            float a = p0[0];
#pragma unroll
            for (int o = 16; o > 0; o >>= 1) a += __shfl_xor_sync(0xffffffffu, a, o);
            w0[0] = __expf(a);
        } else {
#pragma unroll
            for (int v = 0; v < V; v++) {
                float a = p0[v];
#pragma unroll
                for (int o = 1; o < 16; o <<= 1) a += __shfl_xor_sync(0xffffffffu, a, o);
                w0[v] = __expf(a);
            }
        }
#pragma unroll
        for (int v = 0; v < V; v++) {
            den0[v] += w0[v];
            acc0[v].x += w0[v] * f0[v].x; acc0[v].y += w0[v] * f0[v].y;
            acc0[v].z += w0[v] * f0[v].z; acc0[v].w += w0[v] * f0[v].w;
        }
    }
#pragma unroll
    for (int v = 0; v < V; v++) {
        float inv = 1.f / (den0[v] + den1[v] + 1e-16f);
        float4 b = bias4[lane + 32 * v];
        float4 o;
        o.x = fmaxf((acc0[v].x + acc1[v].x) * inv + b.x, 0.f);
        o.y = fmaxf((acc0[v].y + acc1[v].y) * inv + b.y, 0.f);
        o.z = fmaxf((acc0[v].z + acc1[v].z) * inv + b.z, 0.f);
        o.w = fmaxf((acc0[v].w + acc1[v].w) * inv + b.w, 0.f);
        if (ROUND) {
            o.x = __uint_as_float(f2tf32(o.x));
            o.y = __uint_as_float(f2tf32(o.y));
            o.z = __uint_as_float(f2tf32(o.z));
            o.w = __uint_as_float(f2tf32(o.w));
        }
        out4[(long)d * C4 + lane + 32 * v] = o;
    }
}

// ---------------- global mean pool ----------------
__global__ void k_pool(const float* __restrict__ h2, const int* __restrict__ batch) {
    int t = blockIdx.x * blockDim.x + threadIdx.x;
    int w = t >> 5, lane = t & 31;
    if (w >= NN) return;
    int g = batch[w];
#pragma unroll
    for (int c = 0; c < CH2 / 32; c++)
        atomicAdd(&g_sums[g * CH2 + lane + 32 * c], h2[(long)w * CH2 + lane + 32 * c]);
    if (lane == 0) atomicAdd(&g_cnt[g], 1);
}

__global__ void k_final(float* __restrict__ out) {
    int i = blockIdx.x * blockDim.x + threadIdx.x;
    if (i < GG * CH2) {
        int g = i / CH2;
        float c = (float)g_cnt[g];
        out[i] = g_sums[i] / fmaxf(c, 1.f);
    }
}

__global__ void k_reset() {
    int i = blockIdx.x * blockDim.x + threadIdx.x;
    if (i < NN) g_deg[i] = 0;
    if (i < GG * CH2) g_sums[i] = 0.f;
    if (i < GG) g_cnt[i] = 0;
}

// ---------------- launch ----------------
extern "C" void kernel_launch(void* const* d_in, const int* in_sizes, int n_in,
                              void* d_out, int out_size) {
    const float* x     = (const float*)d_in[0];
    const int*   ei    = (const int*)d_in[1];
    const int*   batch = (const int*)d_in[2];
    const float* Wl1   = (const float*)d_in[3];
    const float* bl1   = (const float*)d_in[4];
    const float* Wr1   = (const float*)d_in[5];
    const float* br1   = (const float*)d_in[6];
    const float* att1  = (const float*)d_in[7];
    const float* bias1 = (const float*)d_in[8];
    const float* Wl2   = (const float*)d_in[9];
    const float* bl2   = (const float*)d_in[10];
    const float* Wr2   = (const float*)d_in[11];
    const float* br2   = (const float*)d_in[12];
    const float* att2  = (const float*)d_in[13];
    const float* bias2 = (const float*)d_in[14];

    float *xpad, *w1t, *w2t, *xr1, *h1, *xr2, *h2;
    __half *xl1h, *xl2h;
    cudaGetSymbolAddress((void**)&xpad, g_xpad);
    cudaGetSymbolAddress((void**)&w1t,  g_w1t);
    cudaGetSymbolAddress((void**)&w2t,  g_w2t);
    cudaGetSymbolAddress((void**)&xl1h, g_xl1h);
    cudaGetSymbolAddress((void**)&xr1,  g_xr1);
    cudaGetSymbolAddress((void**)&h1,   g_h1);
    cudaGetSymbolAddress((void**)&xl2h, g_xl2h);
    cudaGetSymbolAddress((void**)&xr2,  g_xr2);
    cudaGetSymbolAddress((void**)&h2,   g_h2);

    int nb = (NN + SCB - 1) / SCB;

    k_prep_x<<<(NNP * 40 + 255) / 256, 256>>>(x);            // #1
    k_prep_w1<<<(40 * 512 + 255) / 256, 256>>>(Wl1, Wr1);    // #2
    k_prep_w2<<<(256 * 256 + 255) / 256, 256>>>(Wl2, Wr2);   // #3

    gemm_tc<40, 44, 1><<<dim3(4, NNP / 128), 256>>>(
        xpad, 40, w1t, 512, bl1, br1, xl1h, xr1, CH1, NN);   // #4 (profiled)

    k_degree<<<(ETOT + 255) / 256, 256>>>(ei);               // #5
    k_scan1<<<nb, SCB>>>();                                  // #6
    k_scan2<<<1, 64>>>(nb);                                  // #7
    k_scan3<<<nb, SCB>>>();                                  // #8
    k_scatter<<<(ETOT + 255) / 256, 256>>>(ei);              // #9

    gat_kernel<4, 256, true><<<(NN + 7) / 8, 256>>>(
        (const uint2*)xl1h, (const float4*)xr1,
        (const float4*)att1, (const float4*)bias1, (float4*)h1);  // #10

    gemm_tc<16, 20, 16><<<dim3(2, NNP / 128), 256>>>(
        h1, 256, w2t, 256, bl2, br2, xl2h, xr2, CH2, NN);    // #11

    gat_kernel<1, 128, false><<<(NN + 7) / 8, 256>>>(
        (const uint2*)xl2h, (const float4*)xr2,
        (const float4*)att2, (const float4*)bias2, (float4*)h2); // #12

    k_pool<<<(NN * 32 + 255) / 256, 256>>>(h2, batch);       // #13
    k_final<<<(GG * CH2 + 255) / 256, 256>>>((float*)d_out); // #14
    k_reset<<<(NN + 255) / 256, 256>>>();                    // #15
}

// round 5
// speedup vs baseline: 1.9417x; 1.0368x over previous
#include <cuda_runtime.h>
#include <cuda_fp16.h>
#include <cstdint>

#define NN    50000
#define NNP   50048            // 391 * 128 (padded rows)
#define NSC   50176            // 49 * 1024 (scan padding)
#define EE    800000
#define ETOT  (EE + NN)
#define GG    128
#define KIN   38
#define CH1   256
#define CH2   128

// ---------------- static device scratch ----------------
__device__ float  g_xpad[NNP * 40];       // tf32-rounded, K padded 38->40
__device__ float  g_w1t [40 * 512];       // tf32 [Wl1|Wr1], rows 38,39 zero
__device__ float  g_w2t [256 * 256];      // tf32 [Wl2|Wr2]
__device__ __half g_xl1h[NN * CH1];
__device__ __half g_xr1h[NN * CH1];
__device__ float  g_h1  [NNP * CH1];      // tf32-rounded; pad rows stay 0
__device__ __half g_xl2h[NN * CH2];
__device__ __half g_xr2h[NN * CH2];
__device__ float  g_h2  [NN * CH2];
__device__ int    g_deg [NSC];            // zero-padded tail
__device__ int    g_off [NSC];            // g_off[NN] == ETOT after scan
__device__ int    g_wcur[NSC];
__device__ int    g_srcs[ETOT];
__device__ float  g_sums[GG * CH2];
__device__ int    g_cnt[GG];

__device__ __forceinline__ uint32_t f2tf32(float f) {
    uint32_t u;
    asm("cvt.rna.tf32.f32 %0, %1;" : "=r"(u) : "f"(f));
    return u;
}

// ---------------- #1: fused prep (x, W1, W2) + degree ----------------
#define PB_X  7820                        // NNP*40/256
#define PB_W1 (PB_X + 80)                 // 40*512/256
#define PB_W2 (PB_W1 + 256)               // 256*256/256
#define PB_DEG (PB_W2 + 3321)             // ceil(ETOT/256)

__global__ void k_prep_deg(const float* __restrict__ x,
                           const float* __restrict__ Wl1, const float* __restrict__ Wr1,
                           const float* __restrict__ Wl2, const float* __restrict__ Wr2,
                           const int* __restrict__ ei) {
    int b = blockIdx.x;
    if (b < PB_X) {
        int i = b * 256 + threadIdx.x;
        int r = i / 40, c = i - r * 40;
        float v = (r < NN && c < KIN) ? x[r * KIN + c] : 0.f;
        g_xpad[i] = __uint_as_float(f2tf32(v));
    } else if (b < PB_W1) {
        int i = (b - PB_X) * 256 + threadIdx.x;
        int r = i >> 9, c = i & 511;
        float v = 0.f;
        if (r < KIN) v = (c < 256) ? Wl1[r * 256 + c] : Wr1[r * 256 + (c - 256)];
        g_w1t[i] = __uint_as_float(f2tf32(v));
    } else if (b < PB_W2) {
        int i = (b - PB_W1) * 256 + threadIdx.x;
        int r = i >> 8, c = i & 255;
        float v = (c < 128) ? Wl2[r * 128 + c] : Wr2[r * 128 + (c - 128)];
        g_w2t[i] = __uint_as_float(f2tf32(v));
    } else {
        int e = (b - PB_W2) * 256 + threadIdx.x;
        if (e >= ETOT) return;
        int dst = (e < EE) ? ei[EE + e] : (e - EE);
        atomicAdd(&g_deg[dst], 1);
    }
}

// ---------------- full CSR scan, one 256-thread block (runs inside gemm1) ---
__device__ void scan_block() {
    __shared__ int warpsum[8];
    int tid = threadIdx.x, lane = tid & 31, wid = tid >> 5;
    int run = 0;
    for (int t = 0; t < 49; t++) {
        int idx = t * 1024 + tid * 4;
        int4 v = *(const int4*)&g_deg[idx];
        int s01 = v.x + v.y;
        int s = s01 + v.z + v.w;
        int inc = s;
#pragma unroll
        for (int o = 1; o < 32; o <<= 1) {
            int u = __shfl_up_sync(0xffffffffu, inc, o);
            if (lane >= o) inc += u;
        }
        if (lane == 31) warpsum[wid] = inc;
        __syncthreads();
        if (wid == 0) {
            int ws = (lane < 8) ? warpsum[lane] : 0;
#pragma unroll
            for (int o = 1; o < 8; o <<= 1) {
                int u = __shfl_up_sync(0xffffffffu, ws, o);
                if (lane >= o) ws += u;
            }
            if (lane < 8) warpsum[lane] = ws;
        }
        __syncthreads();
        int wpref = (wid > 0) ? warpsum[wid - 1] : 0;
        int excl = run + wpref + inc - s;
        int4 o4;
        o4.x = excl; o4.y = excl + v.x; o4.z = excl + s01; o4.w = excl + s01 + v.z;
        *(int4*)&g_off[idx]  = o4;
        *(int4*)&g_wcur[idx] = o4;
        run += warpsum[7];
        __syncthreads();
    }
}

// ---------------- #3: scatter ----------------
__global__ void k_scatter(const int* __restrict__ ei) {
    int e = blockIdx.x * blockDim.x + threadIdx.x;
    if (e >= ETOT) return;
    int src, dst;
    if (e < EE) { src = ei[e]; dst = ei[EE + e]; }
    else        { src = e - EE; dst = src; }
    int pos = atomicAdd(&g_wcur[dst], 1);
    g_srcs[pos] = src;
}

// ---------------- tf32 tensor-core GEMM, fp16 outputs ----------------
#define MMA_TF32(d, a, b)                                                \
    asm volatile(                                                        \
        "mma.sync.aligned.m16n8k8.row.col.f32.tf32.tf32.f32 "            \
        "{%0,%1,%2,%3}, {%4,%5,%6,%7}, {%8,%9}, {%0,%1,%2,%3};"          \
        : "+f"(d[0]), "+f"(d[1]), "+f"(d[2]), "+f"(d[3])                 \
        : "r"(a[0]), "r"(a[1]), "r"(a[2]), "r"(a[3]), "r"(b[0]), "r"(b[1]))

template <int BK, int PA>
__device__ __forceinline__ void load_tile_async(
    float* As, float* Bs, const float* __restrict__ A, int lda,
    const float* __restrict__ Wt, int ldw, int rowBase, int colBase,
    int it, int tid) {
    constexpr int ACH = 128 * BK / 4;
    const float* Ab = A + (long)rowBase * lda + it * BK;
#pragma unroll
    for (int c = tid; c < ACH; c += 256) {
        int row = c / (BK / 4), kc = c - row * (BK / 4);
        uint32_t dst = (uint32_t)__cvta_generic_to_shared(As + row * PA + kc * 4);
        const float* src = Ab + (long)row * lda + kc * 4;
        asm volatile("cp.async.ca.shared.global [%0], [%1], 16;"
                     :: "r"(dst), "l"(src) : "memory");
    }
    constexpr int BCH = BK * 32;
    const float* Bb = Wt + (long)it * BK * ldw + colBase;
#pragma unroll
    for (int c = tid; c < BCH; c += 256) {
        int k = c >> 5, nc = c & 31;
        uint32_t dst = (uint32_t)__cvta_generic_to_shared(Bs + k * 136 + nc * 4);
        const float* src = Bb + (long)k * ldw + nc * 4;
        asm volatile("cp.async.ca.shared.global [%0], [%1], 16;"
                     :: "r"(dst), "l"(src) : "memory");
    }
    asm volatile("cp.async.commit_group;" ::: "memory");
}

// C[M,2N] -> Cl (half, cols [0,N)) and Cr (half, cols [N,2N)). A padded tf32.
// If SCAN: last grid row, block x==0 runs the CSR scan instead of GEMM work.
template <int BK, int PA, int NITER, bool SCAN>
__global__ __launch_bounds__(256) void gemm_tc(
    const float* __restrict__ A, int lda,
    const float* __restrict__ Wt, int ldw,
    const float* __restrict__ b0v, const float* __restrict__ b1v,
    __half* __restrict__ Cl, __half* __restrict__ Cr, int N, int M) {
    if (SCAN && blockIdx.y == gridDim.y - 1) {
        if (blockIdx.x == 0) scan_block();
        return;
    }
    constexpr int STAGES = (NITER > 1) ? 2 : 1;
    constexpr int KSTEPS = BK / 8;
    __shared__ float As[STAGES][128 * PA];
    __shared__ float Bs[STAGES][BK * 136];

    int tid = threadIdx.x, lane = tid & 31, wid = tid >> 5;
    int wm = wid & 3, wn = wid >> 2, l4 = lane >> 2, lq = lane & 3;
    int rowBase = blockIdx.y * 128;
    int colBase = blockIdx.x * 128;

    float c[2][8][4];
#pragma unroll
    for (int mt = 0; mt < 2; mt++)
#pragma unroll
        for (int nt = 0; nt < 8; nt++)
#pragma unroll
            for (int r = 0; r < 4; r++) c[mt][nt][r] = 0.f;

    load_tile_async<BK, PA>(As[0], Bs[0], A, lda, Wt, ldw, rowBase, colBase, 0, tid);

    for (int it = 0; it < NITER; ++it) {
        int buf = it & (STAGES - 1);
        bool has_next = (STAGES == 2) && (it + 1 < NITER);
        if (has_next)
            load_tile_async<BK, PA>(As[(it + 1) & 1], Bs[(it + 1) & 1],
                                    A, lda, Wt, ldw, rowBase, colBase, it + 1, tid);
        if (has_next) asm volatile("cp.async.wait_group 1;" ::: "memory");
        else          asm volatile("cp.async.wait_group 0;" ::: "memory");
        __syncthreads();
        const float* as = As[buf];
        const float* bs = Bs[buf];
#pragma unroll
        for (int ks = 0; ks < KSTEPS; ks++) {
            int kb = ks * 8;
            uint32_t a[2][4];
#pragma unroll
            for (int mt = 0; mt < 2; mt++) {
                int r = wm * 32 + mt * 16 + l4;
                a[mt][0] = __float_as_uint(as[r * PA + kb + lq]);
                a[mt][1] = __float_as_uint(as[(r + 8) * PA + kb + lq]);
                a[mt][2] = __float_as_uint(as[r * PA + kb + lq + 4]);
                a[mt][3] = __float_as_uint(as[(r + 8) * PA + kb + lq + 4]);
            }
            uint32_t b[8][2];
#pragma unroll
            for (int nt = 0; nt < 8; nt++) {
                int n = wn * 64 + nt * 8 + l4;
                b[nt][0] = __float_as_uint(bs[(kb + lq) * 136 + n]);
                b[nt][1] = __float_as_uint(bs[(kb + lq + 4) * 136 + n]);
            }
#pragma unroll
            for (int mt = 0; mt < 2; mt++)
#pragma unroll
                for (int nt = 0; nt < 8; nt++)
                    MMA_TF32(c[mt][nt], a[mt], b[nt]);
        }
        __syncthreads();
    }

    bool left = colBase < N;
    int cb = left ? colBase : colBase - N;
    const float* bias = left ? b0v : b1v;
    __half* C = left ? Cl : Cr;
#pragma unroll
    for (int mt = 0; mt < 2; mt++) {
        int r0 = rowBase + wm * 32 + mt * 16 + l4;
#pragma unroll
        for (int nt = 0; nt < 8; nt++) {
            int colLoc = wn * 64 + nt * 8 + 2 * lq;
            int gc = cb + colLoc;
            float bv0 = bias[gc], bv1 = bias[gc + 1];
            if (r0 < M)
                *(__half2*)&C[(long)r0 * N + gc] =
                    __floats2half2_rn(c[mt][nt][0] + bv0, c[mt][nt][1] + bv1);
            if (r0 + 8 < M)
                *(__half2*)&C[(long)(r0 + 8) * N + gc] =
                    __floats2half2_rn(c[mt][nt][2] + bv0, c[mt][nt][3] + bv1);
        }
    }
}

// ---------------- GATv2: warp-per-dst, channel-blocked lanes ----------------
// Lane owns CPL = CH/32 contiguous channels. One vector LDG per edge per lane.
// CH=256 (H=4, Cph=64): lane's channels all in head lane>>3 -> 3-shuffle reduce.
// CH=128 (H=1): full-warp 5-shuffle reduce.
template <int CPL>
__device__ __forceinline__ void load_half_vec(const __half* p, float* f);

template <> __device__ __forceinline__ void load_half_vec<8>(const __half* p, float* f) {
    uint4 u = *reinterpret_cast<const uint4*>(p);
    float2 a;
    a = __half22float2(*reinterpret_cast<__half2*>(&u.x)); f[0] = a.x; f[1] = a.y;
    a = __half22float2(*reinterpret_cast<__half2*>(&u.y)); f[2] = a.x; f[3] = a.y;
    a = __half22float2(*reinterpret_cast<__half2*>(&u.z)); f[4] = a.x; f[5] = a.y;
    a = __half22float2(*reinterpret_cast<__half2*>(&u.w)); f[6] = a.x; f[7] = a.y;
}
template <> __device__ __forceinline__ void load_half_vec<4>(const __half* p, float* f) {
    uint2 u = *reinterpret_cast<const uint2*>(p);
    float2 a;
    a = __half22float2(*reinterpret_cast<__half2*>(&u.x)); f[0] = a.x; f[1] = a.y;
    a = __half22float2(*reinterpret_cast<__half2*>(&u.y)); f[2] = a.x; f[3] = a.y;
}

template <int CH, bool ROUND>
__global__ __launch_bounds__(256) void gat_kernel(
    const __half* __restrict__ xl, const __half* __restrict__ xr,
    const float* __restrict__ att, const float* __restrict__ bias,
    float* __restrict__ out) {
    constexpr int CPL = CH / 32;
    constexpr int RW  = (CH == 256) ? 8 : 32;   // reduction width (lanes/head)
    int gw   = (blockIdx.x * blockDim.x + threadIdx.x) >> 5;
    int lane = threadIdx.x & 31;
    if (gw >= NN) return;
    const int d = gw;

    float xrv[CPL], atv[CPL], acc[CPL];
    load_half_vec<CPL>(xr + (long)d * CH + lane * CPL, xrv);
#pragma unroll
    for (int j = 0; j < CPL; j++) {
        atv[j] = att[lane * CPL + j];
        acc[j] = 0.f;
    }
    float den = 0.f;

    int beg = g_off[d], end = g_off[d + 1];
    for (int base = beg; base < end; base += 32) {
        int n = end - base; if (n > 32) n = 32;
        int sv = g_srcs[(base + lane < end) ? (base + lane) : (end - 1)];
        int j = 0;
        for (; j + 2 <= n; j += 2) {
            int s0 = __shfl_sync(0xffffffffu, sv, j);
            int s1 = __shfl_sync(0xffffffffu, sv, j + 1);
            float f0[CPL], f1[CPL];
            load_half_vec<CPL>(xl + (long)s0 * CH + lane * CPL, f0);
            load_half_vec<CPL>(xl + (long)s1 * CH + lane * CPL, f1);
            float p0 = 0.f, p1 = 0.f;
#pragma unroll
            for (int k = 0; k < CPL; k++) {
                float t0 = f0[k] + xrv[k];
                t0 = fmaxf(t0, 0.f) + 0.2f * fminf(t0, 0.f);
                p0 = fmaf(t0, atv[k], p0);
                float t1 = f1[k] + xrv[k];
                t1 = fmaxf(t1, 0.f) + 0.2f * fminf(t1, 0.f);
                p1 = fmaf(t1, atv[k], p1);
            }
#pragma unroll
            for (int o = 1; o < RW; o <<= 1) {
                p0 += __shfl_xor_sync(0xffffffffu, p0, o);
                p1 += __shfl_xor_sync(0xffffffffu, p1, o);
            }
            float w0 = __expf(p0), w1 = __expf(p1);
            den += w0 + w1;
#pragma unroll
            for (int k = 0; k < CPL; k++)
                acc[k] = fmaf(w1, f1[k], fmaf(w0, f0[k], acc[k]));
        }
        if (j < n) {
            int s0 = __shfl_sync(0xffffffffu, sv, j);
            float f0[CPL];
            load_half_vec<CPL>(xl + (long)s0 * CH + lane * CPL, f0);
            float p0 = 0.f;
#pragma unroll
            for (int k = 0; k < CPL; k++) {
                float t0 = f0[k] + xrv[k];
                t0 = fmaxf(t0, 0.f) + 0.2f * fminf(t0, 0.f);
                p0 = fmaf(t0, atv[k], p0);
            }
#pragma unroll
            for (int o = 1; o < RW; o <<= 1)
                p0 += __shfl_xor_sync(0xffffffffu, p0, o);
            float w0 = __expf(p0);
            den += w0;
#pragma unroll
            for (int k = 0; k < CPL; k++) acc[k] = fmaf(w0, f0[k], acc[k]);
        }
    }
    float inv = 1.f / (den + 1e-16f);
#pragma unroll
    for (int k = 0; k < CPL; k++) {
        float o = fmaxf(acc[k] * inv + bias[lane * CPL + k], 0.f);
        if (ROUND) o = __uint_as_float(f2tf32(o));
        out[(long)d * CH + lane * CPL + k] = o;
    }
}

// ---------------- global mean pool ----------------
__global__ void k_pool(const float* __restrict__ h2, const int* __restrict__ batch) {
    int t = blockIdx.x * blockDim.x + threadIdx.x;
    int w = t >> 5, lane = t & 31;
    if (w >= NN) return;
    int g = batch[w];
#pragma unroll
    for (int c = 0; c < CH2 / 32; c++)
        atomicAdd(&g_sums[g * CH2 + lane + 32 * c], h2[(long)w * CH2 + lane + 32 * c]);
    if (lane == 0) atomicAdd(&g_cnt[g], 1);
}

__global__ void k_final(float* __restrict__ out) {
    int i = blockIdx.x * blockDim.x + threadIdx.x;
    if (i < GG * CH2) {
        int g = i / CH2;
        float c = (float)g_cnt[g];
        out[i] = g_sums[i] / fmaxf(c, 1.f);
    }
}

__global__ void k_reset() {
    int i = blockIdx.x * blockDim.x + threadIdx.x;
    if (i < NN) g_deg[i] = 0;
    if (i < GG * CH2) g_sums[i] = 0.f;
    if (i < GG) g_cnt[i] = 0;
}

// ---------------- launch ----------------
extern "C" void kernel_launch(void* const* d_in, const int* in_sizes, int n_in,
                              void* d_out, int out_size) {
    const float* x     = (const float*)d_in[0];
    const int*   ei    = (const int*)d_in[1];
    const int*   batch = (const int*)d_in[2];
    const float* Wl1   = (const float*)d_in[3];
    const float* bl1   = (const float*)d_in[4];
    const float* Wr1   = (const float*)d_in[5];
    const float* br1   = (const float*)d_in[6];
    const float* att1  = (const float*)d_in[7];
    const float* bias1 = (const float*)d_in[8];
    const float* Wl2   = (const float*)d_in[9];
    const float* bl2   = (const float*)d_in[10];
    const float* Wr2   = (const float*)d_in[11];
    const float* br2   = (const float*)d_in[12];
    const float* att2  = (const float*)d_in[13];
    const float* bias2 = (const float*)d_in[14];

    float  *xpad, *w1t, *w2t, *h1, *h2;
    __half *xl1h, *xr1h, *xl2h, *xr2h;
    cudaGetSymbolAddress((void**)&xpad, g_xpad);
    cudaGetSymbolAddress((void**)&w1t,  g_w1t);
    cudaGetSymbolAddress((void**)&w2t,  g_w2t);
    cudaGetSymbolAddress((void**)&xl1h, g_xl1h);
    cudaGetSymbolAddress((void**)&xr1h, g_xr1h);
    cudaGetSymbolAddress((void**)&h1,   g_h1);
    cudaGetSymbolAddress((void**)&xl2h, g_xl2h);
    cudaGetSymbolAddress((void**)&xr2h, g_xr2h);
    cudaGetSymbolAddress((void**)&h2,   g_h2);

    // #1: prep x/W1/W2 (tf32) + degree histogram
    k_prep_deg<<<PB_DEG, 256>>>(x, Wl1, Wr1, Wl2, Wr2, ei);

    // #2: layer-1 GEMM (rows 0..390) + CSR scan (extra grid row, block x=0)
    gemm_tc<40, 44, 1, true><<<dim3(4, 392), 256>>>(
        xpad, 40, w1t, 512, bl1, br1, xl1h, xr1h, CH1, NN);

    // #3: scatter edges into CSR
    k_scatter<<<(ETOT + 255) / 256, 256>>>(ei);

    // #4: GAT layer 1  (profiled slot)
    gat_kernel<256, true><<<(NN + 7) / 8, 256>>>(
        xl1h, xr1h, att1, bias1, h1);

    // #5: layer-2 GEMM
    gemm_tc<16, 20, 16, false><<<dim3(2, 391), 256>>>(
        h1, 256, w2t, 256, bl2, br2, xl2h, xr2h, CH2, NN);

    // #6: GAT layer 2
    gat_kernel<128, false><<<(NN + 7) / 8, 256>>>(
        xl2h, xr2h, att2, bias2, h2);

    // #7-#9: pool, finalize, reset invariants
    k_pool<<<(NN * 32 + 255) / 256, 256>>>(h2, batch);
    k_final<<<(GG * CH2 + 255) / 256, 256>>>((float*)d_out);
    k_reset<<<(NN + 255) / 256, 256>>>();
}

// round 6
// speedup vs baseline: 2.3415x; 1.2059x over previous
#include <cuda_runtime.h>
#include <cuda_fp16.h>
#include <cstdint>

#define NN    50000
#define NNP   50048            // 391 * 128 (padded rows)
#define NSC   50176            // 49 * 1024 (scan padding)
#define EE    800000
#define ETOT  (EE + NN)
#define GG    128
#define KIN   38
#define KP1   48               // layer-1 K padded 38->48
#define CH1   256
#define CH2   128

// ---------------- static device scratch ----------------
__device__ __half g_xh  [NNP * KP1];      // fp16 x, K padded
__device__ __half g_w1h [512 * KP1];      // fp16 [Wl1|Wr1] transposed: [col][k]
__device__ __half g_w2h [256 * 256];      // fp16 [Wl2|Wr2] transposed: [col][k]
__device__ __half g_xl1h[NN * CH1];
__device__ __half g_xr1h[NN * CH1];
__device__ __half g_h1h [NNP * CH1];      // GAT1 out fp16; pad rows stay 0
__device__ __half g_xl2h[NN * CH2];
__device__ __half g_xr2h[NN * CH2];
__device__ float  g_h2  [NN * CH2];
__device__ int    g_deg [NSC];            // zero-padded tail
__device__ int    g_off [NSC];
__device__ int    g_wcur[NSC];
__device__ int    g_srcs[ETOT];
__device__ float  g_sums[GG * CH2];
__device__ int    g_cnt[GG];

// ---------------- #1: fused prep (x, W1t, W2t fp16) + degree ----------------
#define PB_X   9384                       // NNP*KP1/256
#define PB_W1  (PB_X + 96)                // 512*KP1/256
#define PB_W2  (PB_W1 + 256)              // 256*256/256
#define PB_DEG (PB_W2 + 3321)             // ceil(ETOT/256)

__global__ void k_prep_deg(const float* __restrict__ x,
                           const float* __restrict__ Wl1, const float* __restrict__ Wr1,
                           const float* __restrict__ Wl2, const float* __restrict__ Wr2,
                           const int* __restrict__ ei) {
    int b = blockIdx.x;
    if (b < PB_X) {
        int i = b * 256 + threadIdx.x;
        int r = i / KP1, c = i - r * KP1;
        float v = (r < NN && c < KIN) ? x[r * KIN + c] : 0.f;
        g_xh[i] = __float2half_rn(v);
    } else if (b < PB_W1) {
        int i = (b - PB_X) * 256 + threadIdx.x;       // [col][k], col<512, k<48
        int col = i / KP1, k = i - col * KP1;
        float v = 0.f;
        if (k < KIN) v = (col < 256) ? Wl1[k * 256 + col] : Wr1[k * 256 + (col - 256)];
        g_w1h[i] = __float2half_rn(v);
    } else if (b < PB_W2) {
        int i = (b - PB_W1) * 256 + threadIdx.x;      // [col][k], col<256, k<256
        int col = i >> 8, k = i & 255;
        float v = (col < 128) ? Wl2[k * 128 + col] : Wr2[k * 128 + (col - 128)];
        g_w2h[i] = __float2half_rn(v);
    } else {
        int e = (b - PB_W2) * 256 + threadIdx.x;
        if (e >= ETOT) return;
        int dst = (e < EE) ? ei[EE + e] : (e - EE);
        atomicAdd(&g_deg[dst], 1);
    }
}

// ---------------- full CSR scan, one 256-thread block (runs inside gemm1) ---
__device__ void scan_block() {
    __shared__ int warpsum[8];
    int tid = threadIdx.x, lane = tid & 31, wid = tid >> 5;
    int run = 0;
    for (int t = 0; t < 49; t++) {
        int idx = t * 1024 + tid * 4;
        int4 v = *(const int4*)&g_deg[idx];
        int s01 = v.x + v.y;
        int s = s01 + v.z + v.w;
        int inc = s;
#pragma unroll
        for (int o = 1; o < 32; o <<= 1) {
            int u = __shfl_up_sync(0xffffffffu, inc, o);
            if (lane >= o) inc += u;
        }
        if (lane == 31) warpsum[wid] = inc;
        __syncthreads();
        if (wid == 0) {
            int ws = (lane < 8) ? warpsum[lane] : 0;
#pragma unroll
            for (int o = 1; o < 8; o <<= 1) {
                int u = __shfl_up_sync(0xffffffffu, ws, o);
                if (lane >= o) ws += u;
            }
            if (lane < 8) warpsum[lane] = ws;
        }
        __syncthreads();
        int wpref = (wid > 0) ? warpsum[wid - 1] : 0;
        int excl = run + wpref + inc - s;
        int4 o4;
        o4.x = excl; o4.y = excl + v.x; o4.z = excl + s01; o4.w = excl + s01 + v.z;
        *(int4*)&g_off[idx]  = o4;
        *(int4*)&g_wcur[idx] = o4;
        run += warpsum[7];
        __syncthreads();
    }
}

// ---------------- #3: scatter ----------------
__global__ void k_scatter(const int* __restrict__ ei) {
    int e = blockIdx.x * blockDim.x + threadIdx.x;
    if (e >= ETOT) return;
    int src, dst;
    if (e < EE) { src = ei[e]; dst = ei[EE + e]; }
    else        { src = e - EE; dst = src; }
    int pos = atomicAdd(&g_wcur[dst], 1);
    g_srcs[pos] = src;
}

// ---------------- fp16 tensor-core GEMM (m16n8k16 HMMA, fp32 accum) --------
// C[M,2N] -> Cl (cols [0,N)), Cr (cols [N,2N)), both fp16 with fp32 bias.
// A [M][lda] fp16 row-major. Bt [2N][ldb] fp16: row = output col, k contiguous.
#define MMA_F16(d, a, b)                                                 \
    asm volatile(                                                        \
        "mma.sync.aligned.m16n8k16.row.col.f32.f16.f16.f32 "             \
        "{%0,%1,%2,%3}, {%4,%5,%6,%7}, {%8,%9}, {%0,%1,%2,%3};"          \
        : "+f"(d[0]), "+f"(d[1]), "+f"(d[2]), "+f"(d[3])                 \
        : "r"(a[0]), "r"(a[1]), "r"(a[2]), "r"(a[3]), "r"(b[0]), "r"(b[1]))

template <int BK, int PAh>
__device__ __forceinline__ void load_tile_h(
    __half* As, __half* Bs, const __half* __restrict__ A, int lda,
    const __half* __restrict__ Bt, int ldb, int rowBase, int colBase,
    int it, int tid) {
    constexpr int CPR = BK / 8;        // 16B chunks per row
    constexpr int NCH = 128 * CPR;
    const __half* Ab = A + (long)rowBase * lda + it * BK;
#pragma unroll
    for (int c = tid; c < NCH; c += 256) {
        int m = c / CPR, kc = (c - m * CPR) * 8;
        uint32_t dst = (uint32_t)__cvta_generic_to_shared(As + m * PAh + kc);
        const void* src = Ab + (long)m * lda + kc;
        asm volatile("cp.async.ca.shared.global [%0], [%1], 16;"
                     :: "r"(dst), "l"(src) : "memory");
    }
    const __half* Bb = Bt + (long)colBase * ldb + it * BK;
#pragma unroll
    for (int c = tid; c < NCH; c += 256) {
        int n = c / CPR, kc = (c - n * CPR) * 8;
        uint32_t dst = (uint32_t)__cvta_generic_to_shared(Bs + n * PAh + kc);
        const void* src = Bb + (long)n * ldb + kc;
        asm volatile("cp.async.ca.shared.global [%0], [%1], 16;"
                     :: "r"(dst), "l"(src) : "memory");
    }
    asm volatile("cp.async.commit_group;" ::: "memory");
}

template <int BK, int PAh, int NITER, bool SCAN>
__global__ __launch_bounds__(256) void gemm_fp16(
    const __half* __restrict__ A, int lda,
    const __half* __restrict__ Bt, int ldb,
    const float* __restrict__ b0v, const float* __restrict__ b1v,
    __half* __restrict__ Cl, __half* __restrict__ Cr, int N, int M) {
    if (SCAN && blockIdx.y == gridDim.y - 1) {
        if (blockIdx.x == 0) scan_block();
        return;
    }
    constexpr int STAGES = (NITER > 1) ? 2 : 1;
    constexpr int KSTEPS = BK / 16;
    __shared__ __align__(16) __half As[STAGES][128 * PAh];
    __shared__ __align__(16) __half Bs[STAGES][128 * PAh];

    int tid = threadIdx.x, lane = tid & 31, wid = tid >> 5;
    int wm = wid & 3, wn = wid >> 2, l4 = lane >> 2, lq = lane & 3;
    int rowBase = blockIdx.y * 128;
    int colBase = blockIdx.x * 128;

    float c[2][8][4];
#pragma unroll
    for (int mt = 0; mt < 2; mt++)
#pragma unroll
        for (int nt = 0; nt < 8; nt++)
#pragma unroll
            for (int r = 0; r < 4; r++) c[mt][nt][r] = 0.f;

    load_tile_h<BK, PAh>(As[0], Bs[0], A, lda, Bt, ldb, rowBase, colBase, 0, tid);

    for (int it = 0; it < NITER; ++it) {
        int buf = it & (STAGES - 1);
        bool has_next = (STAGES == 2) && (it + 1 < NITER);
        if (has_next)
            load_tile_h<BK, PAh>(As[(it + 1) & 1], Bs[(it + 1) & 1],
                                 A, lda, Bt, ldb, rowBase, colBase, it + 1, tid);
        if (has_next) asm volatile("cp.async.wait_group 1;" ::: "memory");
        else          asm volatile("cp.async.wait_group 0;" ::: "memory");
        __syncthreads();
        const __half* as = As[buf];
        const __half* bs = Bs[buf];
#pragma unroll
        for (int ks = 0; ks < KSTEPS; ks++) {
            int kb = ks * 16;
            uint32_t a[2][4];
#pragma unroll
            for (int mt = 0; mt < 2; mt++) {
                int r = wm * 32 + mt * 16 + l4;
                const __half* ap = as + r * PAh + kb + 2 * lq;
                a[mt][0] = *(const uint32_t*)ap;
                a[mt][1] = *(const uint32_t*)(ap + 8 * PAh);
                a[mt][2] = *(const uint32_t*)(ap + 8);
                a[mt][3] = *(const uint32_t*)(ap + 8 * PAh + 8);
            }
            uint32_t b[8][2];
#pragma unroll
            for (int nt = 0; nt < 8; nt++) {
                int n = wn * 64 + nt * 8 + l4;
                const __half* bp = bs + n * PAh + kb + 2 * lq;
                b[nt][0] = *(const uint32_t*)bp;
                b[nt][1] = *(const uint32_t*)(bp + 8);
            }
#pragma unroll
            for (int mt = 0; mt < 2; mt++)
#pragma unroll
                for (int nt = 0; nt < 8; nt++)
                    MMA_F16(c[mt][nt], a[mt], b[nt]);
        }
        __syncthreads();
    }

    bool left = colBase < N;
    int cb = left ? colBase : colBase - N;
    const float* bias = left ? b0v : b1v;
    __half* C = left ? Cl : Cr;
#pragma unroll
    for (int mt = 0; mt < 2; mt++) {
        int r0 = rowBase + wm * 32 + mt * 16 + l4;
#pragma unroll
        for (int nt = 0; nt < 8; nt++) {
            int colLoc = wn * 64 + nt * 8 + 2 * lq;
            int gc = cb + colLoc;
            float bv0 = bias[gc], bv1 = bias[gc + 1];
            if (r0 < M)
                *(__half2*)&C[(long)r0 * N + gc] =
                    __floats2half2_rn(c[mt][nt][0] + bv0, c[mt][nt][1] + bv1);
            if (r0 + 8 < M)
                *(__half2*)&C[(long)(r0 + 8) * N + gc] =
                    __floats2half2_rn(c[mt][nt][2] + bv0, c[mt][nt][3] + bv1);
        }
    }
}

// ---------------- GATv2: warp-per-dst, packed-half2 datapath ----------------
// Lane owns 2*H2 contiguous channels (H2 half2). leaky(t) = max(t, 0.2t) exact.
// CH=256: head = lane>>3 -> 3-shuffle reduce. CH=128: full-warp reduce.
__device__ __forceinline__ __half2 asH2(uint32_t v) {
    return *reinterpret_cast<__half2*>(&v);
}
__device__ __forceinline__ uint32_t h2u(__half2 h) {
    return *reinterpret_cast<uint32_t*>(&h);
}

template <int H2>
__device__ __forceinline__ void load_vec_h2(const __half2* p, __half2* f) {
    if constexpr (H2 == 4) {
        uint4 u = *reinterpret_cast<const uint4*>(p);
        f[0] = asH2(u.x); f[1] = asH2(u.y); f[2] = asH2(u.z); f[3] = asH2(u.w);
    } else {
        uint2 u = *reinterpret_cast<const uint2*>(p);
        f[0] = asH2(u.x); f[1] = asH2(u.y);
    }
}

template <int H2>
__device__ __forceinline__ float edge_logit(const __half2* f, const __half2* xrv,
                                            const __half2* a2, __half2 c02) {
    __half2 p2 = __float2half2_rn(0.f);
#pragma unroll
    for (int j = 0; j < H2; j++) {
        __half2 t = __hadd2(f[j], xrv[j]);
        __half2 l = __hmax2(t, __hmul2(t, c02));
        p2 = __hfma2(l, a2[j], p2);
    }
    float2 pf = __half22float2(p2);
    return pf.x + pf.y;
}

template <int CH, bool OUTHALF>
__global__ __launch_bounds__(256) void gat_h2k(
    const __half2* __restrict__ xl, const __half2* __restrict__ xr,
    const float* __restrict__ att, const float* __restrict__ bias,
    void* __restrict__ outv) {
    constexpr int H2 = CH / 64;          // half2 per lane
    constexpr int RW = (CH == 256) ? 8 : 32;
    constexpr int LD = CH / 2;           // row stride in half2
    int gw   = (blockIdx.x * blockDim.x + threadIdx.x) >> 5;
    int lane = threadIdx.x & 31;
    if (gw >= NN) return;
    const int d = gw;
    const __half2 c02 = __float2half2_rn(0.2f);

    __half2 xrv[H2], a2[H2], acc0[H2], acc1[H2];
    load_vec_h2<H2>(xr + (long)d * LD + lane * H2, xrv);
#pragma unroll
    for (int j = 0; j < H2; j++) {
        a2[j] = __floats2half2_rn(att[lane * 2 * H2 + 2 * j],
                                  att[lane * 2 * H2 + 2 * j + 1]);
        acc0[j] = __float2half2_rn(0.f);
        acc1[j] = __float2half2_rn(0.f);
    }
    float den = 0.f;

    int beg = g_off[d], end = g_off[d + 1];
    for (int base = beg; base < end; base += 32) {
        int n = end - base; if (n > 32) n = 32;
        int sv = g_srcs[(base + lane < end) ? (base + lane) : (end - 1)];
        int j = 0;
        for (; j + 2 <= n; j += 2) {
            int s0 = __shfl_sync(0xffffffffu, sv, j);
            int s1 = __shfl_sync(0xffffffffu, sv, j + 1);
            __half2 f0[H2], f1[H2];
            load_vec_h2<H2>(xl + (long)s0 * LD + lane * H2, f0);
            load_vec_h2<H2>(xl + (long)s1 * LD + lane * H2, f1);
            float p0 = edge_logit<H2>(f0, xrv, a2, c02);
            float p1 = edge_logit<H2>(f1, xrv, a2, c02);
#pragma unroll
            for (int o = 1; o < RW; o <<= 1) {
                p0 += __shfl_xor_sync(0xffffffffu, p0, o);
                p1 += __shfl_xor_sync(0xffffffffu, p1, o);
            }
            float w0 = __expf(p0), w1 = __expf(p1);
            den += w0 + w1;
            __half2 w02 = __float2half2_rn(w0);
            __half2 w12 = __float2half2_rn(w1);
#pragma unroll
            for (int k = 0; k < H2; k++) {
                acc0[k] = __hfma2(w02, f0[k], acc0[k]);
                acc1[k] = __hfma2(w12, f1[k], acc1[k]);
            }
        }
        if (j < n) {
            int s0 = __shfl_sync(0xffffffffu, sv, j);
            __half2 f0[H2];
            load_vec_h2<H2>(xl + (long)s0 * LD + lane * H2, f0);
            float p0 = edge_logit<H2>(f0, xrv, a2, c02);
#pragma unroll
            for (int o = 1; o < RW; o <<= 1)
                p0 += __shfl_xor_sync(0xffffffffu, p0, o);
            float w0 = __expf(p0);
            den += w0;
            __half2 w02 = __float2half2_rn(w0);
#pragma unroll
            for (int k = 0; k < H2; k++)
                acc0[k] = __hfma2(w02, f0[k], acc0[k]);
        }
    }
    float inv = 1.f / (den + 1e-16f);
    float o[2 * H2];
#pragma unroll
    for (int k = 0; k < H2; k++) {
        float2 a = __half22float2(acc0[k]);
        float2 b = __half22float2(acc1[k]);
        o[2 * k]     = fmaxf((a.x + b.x) * inv + bias[lane * 2 * H2 + 2 * k], 0.f);
        o[2 * k + 1] = fmaxf((a.y + b.y) * inv + bias[lane * 2 * H2 + 2 * k + 1], 0.f);
    }
    if constexpr (OUTHALF) {
        __half2* oh = (__half2*)outv;
        uint4 r;
        r.x = h2u(__floats2half2_rn(o[0], o[1]));
        r.y = h2u(__floats2half2_rn(o[2], o[3]));
        r.z = h2u(__floats2half2_rn(o[4], o[5]));
        r.w = h2u(__floats2half2_rn(o[6], o[7]));
        *reinterpret_cast<uint4*>(oh + (long)d * LD + lane * H2) = r;
    } else {
        float* of = (float*)outv;
        *reinterpret_cast<float4*>(of + (long)d * CH + lane * 4) =
            make_float4(o[0], o[1], o[2], o[3]);
    }
}

// ---------------- global mean pool ----------------
__global__ void k_pool(const float* __restrict__ h2, const int* __restrict__ batch) {
    int t = blockIdx.x * blockDim.x + threadIdx.x;
    int w = t >> 5, lane = t & 31;
    if (w >= NN) return;
    int g = batch[w];
#pragma unroll
    for (int c = 0; c < CH2 / 32; c++)
        atomicAdd(&g_sums[g * CH2 + lane + 32 * c], h2[(long)w * CH2 + lane + 32 * c]);
    if (lane == 0) atomicAdd(&g_cnt[g], 1);
}

__global__ void k_final(float* __restrict__ out) {
    int i = blockIdx.x * blockDim.x + threadIdx.x;
    if (i < GG * CH2) {
        int g = i / CH2;
        float c = (float)g_cnt[g];
        out[i] = g_sums[i] / fmaxf(c, 1.f);
    }
}

__global__ void k_reset() {
    int i = blockIdx.x * blockDim.x + threadIdx.x;
    if (i < NN) g_deg[i] = 0;
    if (i < GG * CH2) g_sums[i] = 0.f;
    if (i < GG) g_cnt[i] = 0;
}

// ---------------- launch ----------------
extern "C" void kernel_launch(void* const* d_in, const int* in_sizes, int n_in,
                              void* d_out, int out_size) {
    const float* x     = (const float*)d_in[0];
    const int*   ei    = (const int*)d_in[1];
    const int*   batch = (const int*)d_in[2];
    const float* Wl1   = (const float*)d_in[3];
    const float* bl1   = (const float*)d_in[4];
    const float* Wr1   = (const float*)d_in[5];
    const float* br1   = (const float*)d_in[6];
    const float* att1  = (const float*)d_in[7];
    const float* bias1 = (const float*)d_in[8];
    const float* Wl2   = (const float*)d_in[9];
    const float* bl2   = (const float*)d_in[10];
    const float* Wr2   = (const float*)d_in[11];
    const float* br2   = (const float*)d_in[12];
    const float* att2  = (const float*)d_in[13];
    const float* bias2 = (const float*)d_in[14];

    __half *xh, *w1h, *w2h, *xl1h, *xr1h, *h1h, *xl2h, *xr2h;
    float  *h2;
    cudaGetSymbolAddress((void**)&xh,   g_xh);
    cudaGetSymbolAddress((void**)&w1h,  g_w1h);
    cudaGetSymbolAddress((void**)&w2h,  g_w2h);
    cudaGetSymbolAddress((void**)&xl1h, g_xl1h);
    cudaGetSymbolAddress((void**)&xr1h, g_xr1h);
    cudaGetSymbolAddress((void**)&h1h,  g_h1h);
    cudaGetSymbolAddress((void**)&xl2h, g_xl2h);
    cudaGetSymbolAddress((void**)&xr2h, g_xr2h);
    cudaGetSymbolAddress((void**)&h2,   g_h2);

    // #1: prep x/W1/W2 (fp16) + degree histogram
    k_prep_deg<<<PB_DEG, 256>>>(x, Wl1, Wr1, Wl2, Wr2, ei);

    // #2: layer-1 GEMM (K=48, 3-stage pipeline) + CSR scan (extra grid row)
    gemm_fp16<16, 24, 3, true><<<dim3(4, 392), 256>>>(
        xh, KP1, w1h, KP1, bl1, br1, xl1h, xr1h, CH1, NN);

    // #3: scatter edges into CSR
    k_scatter<<<(ETOT + 255) / 256, 256>>>(ei);

    // #4: GAT layer 1 (profiled slot)
    gat_h2k<256, true><<<(NN + 7) / 8, 256>>>(
        (const __half2*)xl1h, (const __half2*)xr1h, att1, bias1, (void*)h1h);

    // #5: layer-2 GEMM (K=256, BK=32, 8 iters)
    gemm_fp16<32, 40, 8, false><<<dim3(2, 391), 256>>>(
        h1h, 256, w2h, 256, bl2, br2, xl2h, xr2h, CH2, NN);

    // #6: GAT layer 2
    gat_h2k<128, false><<<(NN + 7) / 8, 256>>>(
        (const __half2*)xl2h, (const __half2*)xr2h, att2, bias2, (void*)h2);

    // #7-#9: pool, finalize, reset invariants
    k_pool<<<(NN * 32 + 255) / 256, 256>>>(h2, batch);
    k_final<<<(GG * CH2 + 255) / 256, 256>>>((float*)d_out);
    k_reset<<<(NN + 255) / 256, 256>>>();
}